// round 14
// baseline (speedup 1.0000x reference)
#include <cuda_runtime.h>
#include <cstdint>

// ---------------------------------------------------------------------------
// Problem constants
// ---------------------------------------------------------------------------
#define BSZ    4
#define CCH    256
#define HH     48
#define WW     48
#define NPIX   2304          // 48*48
#define HEADS  8
#define DH     32
#define INNER  256
#define HID    128
#define LOG2E  1.4426950408889634f
#define QSC    (0.17677669529663687f * 1.4426950408889634f)

// padded h1 plane: 50 rows x 52 cols (px (r,c) at (r+1, c+1))
#define PH_ROWS 50
#define PH_COLS 52
#define PH_PLANE (PH_ROWS * PH_COLS)   // 2600

// ---------------------------------------------------------------------------
// Scratch
// ---------------------------------------------------------------------------
__device__ float g_Wt[4 * 256 * 256];          // tf32 patterns: wq,wk,wv,wproj
__device__ float g_xt[BSZ * CCH * NPIX];       // tf32 patterns of x
__device__ float g_luma[BSZ * NPIX];
__device__ float g_biasE[BSZ * NPIX];
__device__ float g_h1p[BSZ * HID * PH_PLANE]; // zero-padded conv1 output
__device__ float g_hmp[6 * BSZ * HID];         // 6 band partials
__device__ float g_film[BSZ * 6 * 256];
__device__ float g_qkv[3 * BSZ * HEADS * NPIX * DH];   // [pr][b][h][n][d]; K,V tf32
__device__ float g_ao[BSZ * HEADS * NPIX * DH];        // tf32-rounded

#define PR_STRIDE (BSZ * HEADS * NPIX * DH)
#define BH_STRIDE (NPIX * DH)
#define B_STRIDE  (HEADS * NPIX * DH)

// ---------------------------------------------------------------------------
// Helpers
// ---------------------------------------------------------------------------
static __device__ __forceinline__ float2 ffma2(float2 a, float2 b, float2 c) {
    float2 d;
    asm("fma.rn.f32x2 %0, %1, %2, %3;"
        : "=l"(reinterpret_cast<unsigned long long&>(d))
        : "l"(reinterpret_cast<unsigned long long&>(a)),
          "l"(reinterpret_cast<unsigned long long&>(b)),
          "l"(reinterpret_cast<unsigned long long&>(c)));
    return d;
}
static __device__ __forceinline__ float ex2f(float x) {
    float r;
    asm("ex2.approx.f32 %0, %1;" : "=f"(r) : "f"(x));
    return r;
}
static __device__ __forceinline__ uint32_t tf32c(float f) {
    uint32_t u;
    asm("cvt.rna.tf32.f32 %0, %1;" : "=r"(u) : "f"(f));
    return u;
}
static __device__ __forceinline__ float tf32f(float f) {
    return __uint_as_float(tf32c(f));
}
static __device__ __forceinline__ void mma_tf32(float* d, const uint32_t* a,
                                                uint32_t b0, uint32_t b1) {
    asm("mma.sync.aligned.m16n8k8.row.col.f32.tf32.tf32.f32 "
        "{%0,%1,%2,%3}, {%4,%5,%6,%7}, {%8,%9}, {%0,%1,%2,%3};"
        : "+f"(d[0]), "+f"(d[1]), "+f"(d[2]), "+f"(d[3])
        : "r"(a[0]), "r"(a[1]), "r"(a[2]), "r"(a[3]), "r"(b0), "r"(b1));
}
static __device__ __forceinline__ void cpasync16(uint32_t smem_addr, const void* gptr) {
    asm volatile("cp.async.cg.shared.global [%0], [%1], 16;"
                 :: "r"(smem_addr), "l"(gptr));
}
#define CP_COMMIT() asm volatile("cp.async.commit_group;")
#define CP_WAIT0()  asm volatile("cp.async.wait_group 0;" ::: "memory")

// ---------------------------------------------------------------------------
// 0) Prep: convert weights + x to tf32 bit patterns (layouts unchanged).
// ---------------------------------------------------------------------------
__global__ void k_prep(const float* __restrict__ wq, const float* __restrict__ wk,
                       const float* __restrict__ wv, const float* __restrict__ wp,
                       const float* __restrict__ x) {
    int i = blockIdx.x * 256 + threadIdx.x;
    float4 v, c;
    if (i < 65536) {
        int slot = i >> 14, j = i & 16383;
        const float* src = (slot == 0) ? wq : (slot == 1) ? wk : (slot == 2) ? wv : wp;
        v = ((const float4*)src)[j];
        c.x = tf32f(v.x); c.y = tf32f(v.y); c.z = tf32f(v.z); c.w = tf32f(v.w);
        ((float4*)g_Wt)[slot * 16384 + j] = c;
    } else {
        int j = i - 65536;
        v = ((const float4*)x)[j];
        c.x = tf32f(v.x); c.y = tf32f(v.y); c.z = tf32f(v.z); c.w = tf32f(v.w);
        ((float4*)g_xt)[j] = c;
    }
}

// ---------------------------------------------------------------------------
// 1) Luma + key bias, fused
// ---------------------------------------------------------------------------
__global__ void k_lumabias(const float* __restrict__ rgb, const float* __restrict__ alpha_p) {
    __shared__ float sy[NPIX];
    __shared__ float pli[2500];
    __shared__ float red[256];
    int b = blockIdx.x, t = threadIdx.x;
    const float* rp = rgb + (size_t)b * 3 * NPIX;
    float lmn = 1e30f, lmx = -1e30f;
#pragma unroll
    for (int k = 0; k < 9; k++) {
        int p = t + k * 256;
        float y = 0.299f * rp[p] + 0.587f * rp[NPIX + p] + 0.114f * rp[2 * NPIX + p];
        sy[p] = y;
        lmn = fminf(lmn, y); lmx = fmaxf(lmx, y);
    }
    red[t] = lmn; __syncthreads();
    for (int s = 128; s > 0; s >>= 1) { if (t < s) red[t] = fminf(red[t], red[t + s]); __syncthreads(); }
    float mn = red[0]; __syncthreads();
    red[t] = lmx; __syncthreads();
    for (int s = 128; s > 0; s >>= 1) { if (t < s) red[t] = fmaxf(red[t], red[t + s]); __syncthreads(); }
    float mx = red[0]; __syncthreads();
    float inv = 1.0f / (mx - mn + 1e-6f);

    for (int i = t; i < 2500; i += 256) pli[i] = 0.f;
    __syncthreads();
#pragma unroll
    for (int k = 0; k < 9; k++) {
        int p = t + k * 256;
        float ln = (sy[p] - mn) * inv;
        g_luma[b * NPIX + p] = ln;
        pli[(p / 48 + 1) * 50 + (p % 48) + 1] = 1.0f - ln;
    }
    __syncthreads();
    float lsum = 0.f;
#pragma unroll
    for (int k = 0; k < 9; k++) {
        int p = t + k * 256;
        int bi = (p / 48 + 1) * 50 + (p % 48) + 1;
        float s = pli[bi - 51] + pli[bi - 50] + pli[bi - 49]
                + pli[bi - 1]  + pli[bi]      + pli[bi + 1]
                + pli[bi + 49] + pli[bi + 50] + pli[bi + 51];
        s *= (1.0f / 9.0f);
        sy[p] = s; lsum += s;
    }
    red[t] = lsum; __syncthreads();
    for (int s = 128; s > 0; s >>= 1) { if (t < s) red[t] += red[t + s]; __syncthreads(); }
    float mean = red[0] * (1.0f / (float)NPIX);
    float a = *alpha_p;
#pragma unroll
    for (int k = 0; k < 9; k++) {
        int p = t + k * 256;
        g_biasE[b * NPIX + p] = a * (sy[p] - mean) * LOG2E;
    }
}

// ---------------------------------------------------------------------------
// 2) Conv1: luma[1ch] -> h1 padded [50x52] planes, 3x3 SAME, ReLU
// ---------------------------------------------------------------------------
__global__ void k_conv1(const float* __restrict__ w1, const float* __restrict__ b1) {
    __shared__ float pl[2500];
    int oc = blockIdx.x, b = blockIdx.y, t = threadIdx.x;
    for (int i = t; i < 2500; i += 256) pl[i] = 0.f;
    __syncthreads();
    const float* L = g_luma + b * NPIX;
#pragma unroll
    for (int k = 0; k < 9; k++) {
        int p = t + k * 256;
        pl[(p / 48 + 1) * 50 + (p % 48) + 1] = L[p];
    }
    __syncthreads();
    float w[9];
#pragma unroll
    for (int i = 0; i < 9; i++) w[i] = w1[oc * 9 + i];
    float bb = b1[oc];
    float* dst = g_h1p + ((size_t)(b * HID + oc)) * PH_PLANE;
    for (int i = t; i < PH_PLANE; i += 256) {
        int r = i / PH_COLS, c = i % PH_COLS;
        if (r == 0 || r == 49 || c == 0 || c >= 49) dst[i] = 0.f;
    }
#pragma unroll
    for (int k = 0; k < 9; k++) {
        int p = t + k * 256;
        int bi = (p / 48 + 1) * 50 + (p % 48) + 1;
        float s = bb
            + pl[bi - 51] * w[0] + pl[bi - 50] * w[1] + pl[bi - 49] * w[2]
            + pl[bi - 1]  * w[3] + pl[bi]      * w[4] + pl[bi + 1]  * w[5]
            + pl[bi + 49] * w[6] + pl[bi + 50] * w[7] + pl[bi + 51] * w[8];
        dst[(p / 48 + 1) * PH_COLS + (p % 48) + 1] = fmaxf(s, 0.f);
    }
}

// ---------------------------------------------------------------------------
// 3) Conv2 + ReLU + spatial mean (band partials). cp.async double-buffered
//    smem tile (10 rows x 52, contiguous in the padded plane): dense staging
//    kills the L1tex wavefront pressure of the scattered per-thread loads.
//    grid (32 ocg, 4 b, 6 band), 96 thr (12x4? -> 12x8 logical).
// ---------------------------------------------------------------------------
#define C2_TILE 520   // 10 * 52 floats, contiguous

__global__ __launch_bounds__(96) void k_conv2mean(const float* __restrict__ w2,
                                                  const float* __restrict__ b2) {
    __shared__ float wsm[128 * 36];           // [ic][tap][oc4]
    __shared__ float hst[2][C2_TILE];         // double-buffered h1 tile
    int ocg = blockIdx.x, b = blockIdx.y, band = blockIdx.z;
    int t = threadIdx.x;
    int ty = t / 12, tx = t % 12;

    for (int i = t; i < 128 * 36; i += 96) {
        int ic = i / 36, r = i % 36;
        int tap = r >> 2, oc = r & 3;
        wsm[i] = w2[(((ocg * 4 + oc) * 128) + ic) * 9 + tap];
    }

    const float* srcb = g_h1p + (size_t)b * HID * PH_PLANE + band * 8 * PH_COLS;
    uint32_t hst0 = (uint32_t)__cvta_generic_to_shared(&hst[0][0]);
    uint32_t hst1 = (uint32_t)__cvta_generic_to_shared(&hst[1][0]);

    // preload ic=0 tile into stage 0 (130 float4)
#pragma unroll
    for (int i = t; i < 130; i += 96) cpasync16(hst0 + i * 16, srcb + i * 4);
    CP_COMMIT();
    CP_WAIT0();
    __syncthreads();

    int base0 = ty * PH_COLS + tx * 4;
    float2 acc2[4][2];
#pragma unroll
    for (int j = 0; j < 4; j++) { acc2[j][0] = make_float2(0.f, 0.f); acc2[j][1] = make_float2(0.f, 0.f); }

    for (int ic = 0; ic < 128; ++ic) {
        int cu = ic & 1;
        if (ic < 127) {
            const float* sn = srcb + (size_t)(ic + 1) * PH_PLANE;
            uint32_t dst = cu ? hst0 : hst1;
#pragma unroll
            for (int i = t; i < 130; i += 96) cpasync16(dst + i * 16, sn + i * 4);
            CP_COMMIT();
        }
        const float* hs = hst[cu];
        const float4* wv = (const float4*)&wsm[ic * 36];
#pragma unroll
        for (int r = 0; r < 3; r++) {
            float4 h4 = *(const float4*)&hs[base0 + r * PH_COLS];
            float2 h2 = *(const float2*)&hs[base0 + r * PH_COLS + 4];
            float v[6] = { h4.x, h4.y, h4.z, h4.w, h2.x, h2.y };
#pragma unroll
            for (int tc = 0; tc < 3; tc++) {
                float4 w4 = wv[r * 3 + tc];
                float2 wlo = make_float2(w4.x, w4.y), whi = make_float2(w4.z, w4.w);
#pragma unroll
                for (int j = 0; j < 4; j++) {
                    float vv = v[j + tc];
                    float2 tt = make_float2(vv, vv);
                    acc2[j][0] = ffma2(tt, wlo, acc2[j][0]);
                    acc2[j][1] = ffma2(tt, whi, acc2[j][1]);
                }
            }
        }
        if (ic < 127) CP_WAIT0();
        __syncthreads();
    }
    float bb[4] = { b2[ocg * 4 + 0], b2[ocg * 4 + 1], b2[ocg * 4 + 2], b2[ocg * 4 + 3] };
    float prt[4];
#pragma unroll
    for (int oc = 0; oc < 4; oc++) prt[oc] = 0.f;
#pragma unroll
    for (int j = 0; j < 4; j++) {
        prt[0] += fmaxf(acc2[j][0].x + bb[0], 0.f);
        prt[1] += fmaxf(acc2[j][0].y + bb[1], 0.f);
        prt[2] += fmaxf(acc2[j][1].x + bb[2], 0.f);
        prt[3] += fmaxf(acc2[j][1].y + bb[3], 0.f);
    }
    for (int oc = 0; oc < 4; oc++) {
        wsm[t] = prt[oc];
        __syncthreads();
        if (t < 32) {
            float v = wsm[t] + wsm[t + 32] + wsm[t + 64];
            v += __shfl_xor_sync(0xffffffffu, v, 16);
            v += __shfl_xor_sync(0xffffffffu, v, 8);
            v += __shfl_xor_sync(0xffffffffu, v, 4);
            v += __shfl_xor_sync(0xffffffffu, v, 2);
            v += __shfl_xor_sync(0xffffffffu, v, 1);
            if (t == 0) g_hmp[(band * BSZ + b) * HID + ocg * 4 + oc] = v * (1.0f / (float)NPIX);
        }
        __syncthreads();
    }
}

// ---------------------------------------------------------------------------
// 4) FiLM parameter GEMVs (sums 6 conv2 band partials)
// ---------------------------------------------------------------------------
struct FilmArgs { const float* w[6]; const float* b[6]; };

__global__ void k_film(FilmArgs fa) {
    int s = blockIdx.x, b = blockIdx.y, o = threadIdx.x;
    __shared__ float sh[HID];
    if (threadIdx.x < HID) {
        int h = threadIdx.x;
        float acc = 0.f;
#pragma unroll
        for (int bd = 0; bd < 6; bd++) acc += g_hmp[(bd * BSZ + b) * HID + h];
        sh[h] = acc;
    }
    __syncthreads();
    const float* W = fa.w[s] + o * HID;
    float acc = fa.b[s][o];
#pragma unroll 8
    for (int h = 0; h < HID; h++) acc += sh[h] * W[h];
    g_film[(b * 6 + s) * 256 + o] = acc;
}

// ---------------------------------------------------------------------------
// 5) QKV GEMM via tf32 mma (+ bias + FiLM)
// ---------------------------------------------------------------------------
#define AW_STRIDE 36
#define BX_STRIDE 72

__global__ __launch_bounds__(256) void k_qkv(const float* __restrict__ bq,
                                             const float* __restrict__ bk,
                                             const float* __restrict__ bv) {
    __shared__ float wsm[128 * AW_STRIDE];
    __shared__ float xsm[32 * BX_STRIDE];
    int ntb = blockIdx.x, mt = blockIdx.y, z = blockIdx.z;
    int pr = z >> 2, b = z & 3;
    int t = threadIdx.x, warp = t >> 5, lane = t & 31;
    int gid = lane >> 2, tig = lane & 3;
    int n0 = ntb * 64;

    const float* W = g_Wt + pr * 65536 + mt * 128 * 256;
    const float* xb = g_xt + (size_t)b * CCH * NPIX;

    float s[8][4];
#pragma unroll
    for (int i = 0; i < 8; i++)
#pragma unroll
        for (int j = 0; j < 4; j++) s[i][j] = 0.f;

    for (int kk = 0; kk < 256; kk += 32) {
        if (kk) __syncthreads();
#pragma unroll
        for (int j = 0; j < 4; j++) {
            int idx = t + j * 256;
            int o = idx >> 3, cg = idx & 7;
            *(float4*)&wsm[o * AW_STRIDE + cg * 4] = *(const float4*)&W[o * 256 + kk + cg * 4];
        }
#pragma unroll
        for (int j = 0; j < 2; j++) {
            int idx = t + j * 256;
            int c = idx >> 4, ng = idx & 15;
            *(float4*)&xsm[c * BX_STRIDE + ng * 4] =
                *(const float4*)&xb[(size_t)(kk + c) * NPIX + n0 + ng * 4];
        }
        __syncthreads();
#pragma unroll
        for (int ks = 0; ks < 4; ks++) {
            uint32_t a[4];
            int ab = (warp * 16 + gid) * AW_STRIDE + ks * 8 + tig;
            a[0] = __float_as_uint(wsm[ab]);
            a[1] = __float_as_uint(wsm[ab + 8 * AW_STRIDE]);
            a[2] = __float_as_uint(wsm[ab + 4]);
            a[3] = __float_as_uint(wsm[ab + 8 * AW_STRIDE + 4]);
#pragma unroll
            for (int nt = 0; nt < 8; nt++) {
                int bbx = (ks * 8 + tig) * BX_STRIDE + nt * 8 + gid;
                mma_tf32(s[nt], a, __float_as_uint(xsm[bbx]),
                         __float_as_uint(xsm[bbx + 4 * BX_STRIDE]));
            }
        }
    }
    int o0 = mt * 128 + warp * 16 + gid, o1 = o0 + 8;
    const float* fg  = g_film + (b * 6 + 2 * pr) * 256;
    const float* fb2 = g_film + (b * 6 + 2 * pr + 1) * 256;
    const float* bias = (pr == 0) ? bq : (pr == 1) ? bk : bv;
    float g0 = fg[o0], g1 = fg[o1], e0 = fb2[o0], e1 = fb2[o1];
    float i0 = bias[o0], i1 = bias[o1];
    int h0 = o0 >> 5, d0 = o0 & 31, h1 = o1 >> 5, d1 = o1 & 31;
    float* outb = g_qkv + (size_t)pr * PR_STRIDE + (size_t)b * B_STRIDE;
    bool rnd = (pr != 0);
#pragma unroll
    for (int nt = 0; nt < 8; nt++) {
        int n = n0 + nt * 8 + 2 * tig;
        float v00 = g0 * (s[nt][0] + i0) + e0;
        float v01 = g0 * (s[nt][1] + i0) + e0;
        float v10 = g1 * (s[nt][2] + i1) + e1;
        float v11 = g1 * (s[nt][3] + i1) + e1;
        if (rnd) { v00 = tf32f(v00); v01 = tf32f(v01); v10 = tf32f(v10); v11 = tf32f(v11); }
        outb[((size_t)h0 * NPIX + n) * 32 + d0]     = v00;
        outb[((size_t)h0 * NPIX + n + 1) * 32 + d0] = v01;
        outb[((size_t)h1 * NPIX + n) * 32 + d1]     = v10;
        outb[((size_t)h1 * NPIX + n + 1) * 32 + d1] = v11;
    }
}

// ---------------------------------------------------------------------------
// 6) Flash attention with tf32 mma, cp.async double-buffered K/V/bias.
// ---------------------------------------------------------------------------
#define KS_STRIDE 36
#define VS_STRIDE 40
#define PS_STRIDE 68
#define STAGE_F   (64 * KS_STRIDE + 64 * VS_STRIDE)     // 4864 floats
#define PSM_OFF   (2 * STAGE_F)                          // 9728
#define BSM_OFF   (PSM_OFF + 8 * 16 * PS_STRIDE)         // 18432
#define ATTN_SMEM ((BSM_OFF + 128) * 4)                  // 74240 B

__global__ __launch_bounds__(256) void k_attn() {
    extern __shared__ float smp[];
    float* psm = smp + PSM_OFF;

    int t = threadIdx.x;
    int warp = t >> 5, lane = t & 31;
    int gid = lane >> 2, tig = lane & 3;
    int bh = blockIdx.y;
    int b = bh >> 3;

    const float* Qb = g_qkv + (size_t)bh * BH_STRIDE;
    const float* Kb = g_qkv + (size_t)PR_STRIDE + (size_t)bh * BH_STRIDE;
    const float* Vb = g_qkv + (size_t)2 * PR_STRIDE + (size_t)bh * BH_STRIDE;
    const float* bE = g_biasE + b * NPIX;

    uint32_t smb = (uint32_t)__cvta_generic_to_shared(smp);

    int qr = blockIdx.x * 128 + warp * 16 + gid;

    uint32_t aq[4][4];
#pragma unroll
    for (int ks = 0; ks < 4; ks++) {
        aq[ks][0] = tf32c(Qb[(size_t)qr * 32 + ks * 8 + tig] * QSC);
        aq[ks][1] = tf32c(Qb[(size_t)(qr + 8) * 32 + ks * 8 + tig] * QSC);
        aq[ks][2] = tf32c(Qb[(size_t)qr * 32 + ks * 8 + tig + 4] * QSC);
        aq[ks][3] = tf32c(Qb[(size_t)(qr + 8) * 32 + ks * 8 + tig + 4] * QSC);
    }

    float o[4][4];
#pragma unroll
    for (int i = 0; i < 4; i++)
#pragma unroll
        for (int j = 0; j < 4; j++) o[i][j] = 0.f;
    float m0 = -1e30f, m1 = -1e30f, l0 = 0.f, l1 = 0.f;

    float* pw = psm + warp * 16 * PS_STRIDE;

    {
        const float4* Kg = (const float4*)Kb;
        const float4* Vg = (const float4*)Vb;
#pragma unroll
        for (int i = t; i < 512; i += 256) {
            int key = i >> 3, dq = i & 7;
            cpasync16(smb + (key * KS_STRIDE + dq * 4) * 4, Kg + i);
            cpasync16(smb + (64 * KS_STRIDE + key * VS_STRIDE + dq * 4) * 4, Vg + i);
        }
        if (t < 16) cpasync16(smb + (BSM_OFF + t * 4) * 4, bE + t * 4);
        CP_COMMIT();
        CP_WAIT0();
    }
    __syncthreads();

    for (int nk = 0; nk < 36; ++nk) {
        int cu = nk & 1, nx = cu ^ 1;
        if (nk < 35) {
            const float4* Kg = (const float4*)Kb + (nk + 1) * 512;
            const float4* Vg = (const float4*)Vb + (nk + 1) * 512;
            uint32_t ksu = smb + nx * STAGE_F * 4;
            uint32_t vsu = ksu + 64 * KS_STRIDE * 4;
#pragma unroll
            for (int i = t; i < 512; i += 256) {
                int key = i >> 3, dq = i & 7;
                cpasync16(ksu + (key * KS_STRIDE + dq * 4) * 4, Kg + i);
                cpasync16(vsu + (key * VS_STRIDE + dq * 4) * 4, Vg + i);
            }
            if (t < 16) cpasync16(smb + (BSM_OFF + nx * 64 + t * 4) * 4,
                                  bE + (nk + 1) * 64 + t * 4);
            CP_COMMIT();
        }

        const float* ksm = smp + cu * STAGE_F;
        const float* vsm = ksm + 64 * KS_STRIDE;
        const float* bsm = smp + BSM_OFF + cu * 64;

        float s[8][4];
#pragma unroll
        for (int nt = 0; nt < 8; nt++)
#pragma unroll
            for (int c = 0; c < 4; c++) s[nt][c] = 0.f;
#pragma unroll
        for (int ks = 0; ks < 4; ks++) {
#pragma unroll
            for (int nt = 0; nt < 8; nt++) {
                int kb = (nt * 8 + gid) * KS_STRIDE + ks * 8 + tig;
                uint32_t b0 = __float_as_uint(ksm[kb]);
                uint32_t b1 = __float_as_uint(ksm[kb + 4]);
                mma_tf32(s[nt], aq[ks], b0, b1);
            }
        }
        float mx0 = -1e30f, mx1 = -1e30f;
#pragma unroll
        for (int nt = 0; nt < 8; nt++) {
            float b0v = bsm[nt * 8 + 2 * tig];
            float b1v = bsm[nt * 8 + 2 * tig + 1];
            s[nt][0] += b0v; s[nt][1] += b1v;
            s[nt][2] += b0v; s[nt][3] += b1v;
            mx0 = fmaxf(mx0, fmaxf(s[nt][0], s[nt][1]));
            mx1 = fmaxf(mx1, fmaxf(s[nt][2], s[nt][3]));
        }
        mx0 = fmaxf(mx0, __shfl_xor_sync(0xffffffffu, mx0, 1));
        mx0 = fmaxf(mx0, __shfl_xor_sync(0xffffffffu, mx0, 2));
        mx1 = fmaxf(mx1, __shfl_xor_sync(0xffffffffu, mx1, 1));
        mx1 = fmaxf(mx1, __shfl_xor_sync(0xffffffffu, mx1, 2));

        float mn0 = fmaxf(m0, mx0), mn1 = fmaxf(m1, mx1);
        float c0 = ex2f(m0 - mn0), c1 = ex2f(m1 - mn1);
        m0 = mn0; m1 = mn1;

        float rs0 = 0.f, rs1 = 0.f;
#pragma unroll
        for (int nt = 0; nt < 8; nt++) {
            float p00 = ex2f(s[nt][0] - mn0);
            float p01 = ex2f(s[nt][1] - mn0);
            float p10 = ex2f(s[nt][2] - mn1);
            float p11 = ex2f(s[nt][3] - mn1);
            rs0 += p00 + p01; rs1 += p10 + p11;
            float2 lo, hi;
            lo.x = tf32f(p00); lo.y = tf32f(p01);
            hi.x = tf32f(p10); hi.y = tf32f(p11);
            *(float2*)&pw[gid * PS_STRIDE + nt * 8 + 2 * tig] = lo;
            *(float2*)&pw[(gid + 8) * PS_STRIDE + nt * 8 + 2 * tig] = hi;
        }
        rs0 += __shfl_xor_sync(0xffffffffu, rs0, 1);
        rs0 += __shfl_xor_sync(0xffffffffu, rs0, 2);
        rs1 += __shfl_xor_sync(0xffffffffu, rs1, 1);
        rs1 += __shfl_xor_sync(0xffffffffu, rs1, 2);
        l0 = l0 * c0 + rs0;
        l1 = l1 * c1 + rs1;
#pragma unroll
        for (int nt = 0; nt < 4; nt++) {
            o[nt][0] *= c0; o[nt][1] *= c0;
            o[nt][2] *= c1; o[nt][3] *= c1;
        }
        __syncwarp();

#pragma unroll
        for (int ks = 0; ks < 8; ks++) {
            uint32_t a[4];
            a[0] = __float_as_uint(pw[gid * PS_STRIDE + ks * 8 + tig]);
            a[1] = __float_as_uint(pw[(gid + 8) * PS_STRIDE + ks * 8 + tig]);
            a[2] = __float_as_uint(pw[gid * PS_STRIDE + ks * 8 + tig + 4]);
            a[3] = __float_as_uint(pw[(gid + 8) * PS_STRIDE + ks * 8 + tig + 4]);
#pragma unroll
            for (int nt = 0; nt < 4; nt++) {
                int vb = (ks * 8 + tig) * VS_STRIDE + nt * 8 + gid;
                uint32_t b0 = __float_as_uint(vsm[vb]);
                uint32_t b1 = __float_as_uint(vsm[vb + 4 * VS_STRIDE]);
                mma_tf32(o[nt], a, b0, b1);
            }
        }
        if (nk < 35) CP_WAIT0();
        __syncthreads();
    }

    float i0 = 1.0f / l0, i1 = 1.0f / l1;
    float* AO = g_ao + (size_t)bh * BH_STRIDE;
#pragma unroll
    for (int nt = 0; nt < 4; nt++) {
        float2 lo = make_float2(tf32f(o[nt][0] * i0), tf32f(o[nt][1] * i0));
        float2 hi = make_float2(tf32f(o[nt][2] * i1), tf32f(o[nt][3] * i1));
        *(float2*)&AO[(size_t)qr * 32 + nt * 8 + 2 * tig] = lo;
        *(float2*)&AO[(size_t)(qr + 8) * 32 + nt * 8 + 2 * tig] = hi;
    }
}

// ---------------------------------------------------------------------------
// 7) Output projection via tf32 mma
// ---------------------------------------------------------------------------
__global__ __launch_bounds__(256) void k_proj(const float* __restrict__ bproj,
                                              float* __restrict__ out) {
    __shared__ float wsm[128 * AW_STRIDE];
    __shared__ float bsm2[32 * BX_STRIDE];
    int ntb = blockIdx.x, mt = blockIdx.y, b = blockIdx.z;
    int t = threadIdx.x, warp = t >> 5, lane = t & 31;
    int gid = lane >> 2, tig = lane & 3;
    int n0 = ntb * 64;

    const float* W = g_Wt + 3 * 65536 + mt * 128 * 256;
    const float* AOb = g_ao + (size_t)b * B_STRIDE;

    float s[8][4];
#pragma unroll
    for (int i = 0; i < 8; i++)
#pragma unroll
        for (int j = 0; j < 4; j++) s[i][j] = 0.f;

    for (int kk = 0; kk < 256; kk += 32) {
        if (kk) __syncthreads();
#pragma unroll
        for (int j = 0; j < 4; j++) {
            int idx = t + j * 256;
            int o = idx >> 3, cg = idx & 7;
            *(float4*)&wsm[o * AW_STRIDE + cg * 4] = *(const float4*)&W[o * 256 + kk + cg * 4];
        }
#pragma unroll
        for (int j = 0; j < 8; j++) {
            int idx = t + j * 256;
            int c = idx >> 6, ng = idx & 63;
            int o = kk + c;
            bsm2[c * BX_STRIDE + ng] =
                AOb[((size_t)(o >> 5) * NPIX + n0 + ng) * 32 + (o & 31)];
        }
        __syncthreads();
#pragma unroll
        for (int ks = 0; ks < 4; ks++) {
            uint32_t a[4];
            int ab = (warp * 16 + gid) * AW_STRIDE + ks * 8 + tig;
            a[0] = __float_as_uint(wsm[ab]);
            a[1] = __float_as_uint(wsm[ab + 8 * AW_STRIDE]);
            a[2] = __float_as_uint(wsm[ab + 4]);
            a[3] = __float_as_uint(wsm[ab + 8 * AW_STRIDE + 4]);
#pragma unroll
            for (int nt = 0; nt < 8; nt++) {
                int bbx = (ks * 8 + tig) * BX_STRIDE + nt * 8 + gid;
                mma_tf32(s[nt], a, __float_as_uint(bsm2[bbx]),
                         __float_as_uint(bsm2[bbx + 4 * BX_STRIDE]));
            }
        }
    }
    int o0 = mt * 128 + warp * 16 + gid, o1 = o0 + 8;
    float bp0 = bproj[o0], bp1 = bproj[o1];
#pragma unroll
    for (int nt = 0; nt < 8; nt++) {
        int n = n0 + nt * 8 + 2 * tig;
        *(float2*)&out[((size_t)(b * 256 + o0)) * NPIX + n] =
            make_float2(s[nt][0] + bp0, s[nt][1] + bp0);
        *(float2*)&out[((size_t)(b * 256 + o1)) * NPIX + n] =
            make_float2(s[nt][2] + bp1, s[nt][3] + bp1);
    }
}

// ---------------------------------------------------------------------------
// launch (k_prep forked to a second stream, joined before k_qkv)
// ---------------------------------------------------------------------------
extern "C" void kernel_launch(void* const* d_in, const int* in_sizes, int n_in,
                              void* d_out, int out_size) {
    const float* x     = (const float*)d_in[0];
    const float* rgb   = (const float*)d_in[1];
    const float* wq    = (const float*)d_in[2];
    const float* bq    = (const float*)d_in[3];
    const float* wk    = (const float*)d_in[4];
    const float* bk    = (const float*)d_in[5];
    const float* wv    = (const float*)d_in[6];
    const float* bv    = (const float*)d_in[7];
    const float* wproj = (const float*)d_in[8];
    const float* bproj = (const float*)d_in[9];
    const float* c1w   = (const float*)d_in[10];
    const float* c1b   = (const float*)d_in[11];
    const float* c2w   = (const float*)d_in[12];
    const float* c2b   = (const float*)d_in[13];
    const float* alpha = (const float*)d_in[26];

    FilmArgs fa;
    fa.w[0] = (const float*)d_in[14]; fa.b[0] = (const float*)d_in[15];
    fa.w[1] = (const float*)d_in[16]; fa.b[1] = (const float*)d_in[17];
    fa.w[2] = (const float*)d_in[18]; fa.b[2] = (const float*)d_in[19];
    fa.w[3] = (const float*)d_in[20]; fa.b[3] = (const float*)d_in[21];
    fa.w[4] = (const float*)d_in[22]; fa.b[4] = (const float*)d_in[23];
    fa.w[5] = (const float*)d_in[24]; fa.b[5] = (const float*)d_in[25];

    static bool init_done = false;
    static cudaStream_t s2;
    static cudaEvent_t evFork, evJoin;
    if (!init_done) {
        cudaFuncSetAttribute(k_attn, cudaFuncAttributeMaxDynamicSharedMemorySize, ATTN_SMEM);
        cudaStreamCreateWithFlags(&s2, cudaStreamNonBlocking);
        cudaEventCreateWithFlags(&evFork, cudaEventDisableTiming);
        cudaEventCreateWithFlags(&evJoin, cudaEventDisableTiming);
        init_done = true;
    }

    // fork: k_prep on s2, concurrent with the conv/FiLM chain on the default stream
    cudaEventRecord(evFork, 0);
    cudaStreamWaitEvent(s2, evFork, 0);
    k_prep<<<2560, 256, 0, s2>>>(wq, wk, wv, wproj, x);
    cudaEventRecord(evJoin, s2);

    k_lumabias<<<BSZ, 256>>>(rgb, alpha);
    k_conv1<<<dim3(HID, BSZ), 256>>>(c1w, c1b);
    k_conv2mean<<<dim3(32, BSZ, 6), 96>>>(c2w, c2b);
    k_film<<<dim3(6, BSZ), 256>>>(fa);

    // join: k_qkv needs g_Wt/g_xt from k_prep
    cudaStreamWaitEvent(0, evJoin, 0);
    k_qkv<<<dim3(36, 2, 12), 256>>>(bq, bk, bv);
    k_attn<<<dim3(18, 32), 256, ATTN_SMEM>>>();
    k_proj<<<dim3(36, 2, 4), 256>>>(bproj, (float*)d_out);
}

// round 15
// speedup vs baseline: 1.0115x; 1.0115x over previous
#include <cuda_runtime.h>
#include <cstdint>

// ---------------------------------------------------------------------------
// Problem constants
// ---------------------------------------------------------------------------
#define BSZ    4
#define CCH    256
#define HH     48
#define WW     48
#define NPIX   2304          // 48*48
#define HEADS  8
#define DH     32
#define INNER  256
#define HID    128
#define LOG2E  1.4426950408889634f
#define QSC    (0.17677669529663687f * 1.4426950408889634f)

// padded h1 plane: 50 rows x 52 cols (px (r,c) at (r+1, c+1))
#define PH_ROWS 50
#define PH_COLS 52
#define PH_PLANE (PH_ROWS * PH_COLS)   // 2600

// ---------------------------------------------------------------------------
// Scratch
// ---------------------------------------------------------------------------
__device__ float g_Wt[4 * 256 * 256];          // tf32 patterns: wq,wk,wv,wproj
__device__ float g_xt[BSZ * CCH * NPIX];       // tf32 patterns of x
__device__ float g_luma[BSZ * NPIX];
__device__ float g_biasE[BSZ * NPIX];
__device__ float g_h1p[BSZ * HID * PH_PLANE]; // zero-padded conv1 output
__device__ float g_hmp[6 * BSZ * HID];         // 6 band partials
__device__ float g_film[BSZ * 6 * 256];
__device__ float g_qkv[3 * BSZ * HEADS * NPIX * DH];   // [pr][b][h][n][d]; K,V tf32
__device__ float g_ao[BSZ * HEADS * NPIX * DH];        // tf32-rounded

#define PR_STRIDE (BSZ * HEADS * NPIX * DH)
#define BH_STRIDE (NPIX * DH)
#define B_STRIDE  (HEADS * NPIX * DH)

// ---------------------------------------------------------------------------
// Helpers
// ---------------------------------------------------------------------------
static __device__ __forceinline__ float2 ffma2(float2 a, float2 b, float2 c) {
    float2 d;
    asm("fma.rn.f32x2 %0, %1, %2, %3;"
        : "=l"(reinterpret_cast<unsigned long long&>(d))
        : "l"(reinterpret_cast<unsigned long long&>(a)),
          "l"(reinterpret_cast<unsigned long long&>(b)),
          "l"(reinterpret_cast<unsigned long long&>(c)));
    return d;
}
static __device__ __forceinline__ float ex2f(float x) {
    float r;
    asm("ex2.approx.f32 %0, %1;" : "=f"(r) : "f"(x));
    return r;
}
static __device__ __forceinline__ uint32_t tf32c(float f) {
    uint32_t u;
    asm("cvt.rna.tf32.f32 %0, %1;" : "=r"(u) : "f"(f));
    return u;
}
static __device__ __forceinline__ float tf32f(float f) {
    return __uint_as_float(tf32c(f));
}
static __device__ __forceinline__ void mma_tf32(float* d, const uint32_t* a,
                                                uint32_t b0, uint32_t b1) {
    asm("mma.sync.aligned.m16n8k8.row.col.f32.tf32.tf32.f32 "
        "{%0,%1,%2,%3}, {%4,%5,%6,%7}, {%8,%9}, {%0,%1,%2,%3};"
        : "+f"(d[0]), "+f"(d[1]), "+f"(d[2]), "+f"(d[3])
        : "r"(a[0]), "r"(a[1]), "r"(a[2]), "r"(a[3]), "r"(b0), "r"(b1));
}
static __device__ __forceinline__ void cpasync16(uint32_t smem_addr, const void* gptr) {
    asm volatile("cp.async.cg.shared.global [%0], [%1], 16;"
                 :: "r"(smem_addr), "l"(gptr));
}
#define CP_COMMIT() asm volatile("cp.async.commit_group;")
#define CP_WAIT0()  asm volatile("cp.async.wait_group 0;" ::: "memory")

// ---------------------------------------------------------------------------
// 0) Prep: convert weights + x to tf32 bit patterns (layouts unchanged).
// ---------------------------------------------------------------------------
__global__ void k_prep(const float* __restrict__ wq, const float* __restrict__ wk,
                       const float* __restrict__ wv, const float* __restrict__ wp,
                       const float* __restrict__ x) {
    int i = blockIdx.x * 256 + threadIdx.x;
    float4 v, c;
    if (i < 65536) {
        int slot = i >> 14, j = i & 16383;
        const float* src = (slot == 0) ? wq : (slot == 1) ? wk : (slot == 2) ? wv : wp;
        v = ((const float4*)src)[j];
        c.x = tf32f(v.x); c.y = tf32f(v.y); c.z = tf32f(v.z); c.w = tf32f(v.w);
        ((float4*)g_Wt)[slot * 16384 + j] = c;
    } else {
        int j = i - 65536;
        v = ((const float4*)x)[j];
        c.x = tf32f(v.x); c.y = tf32f(v.y); c.z = tf32f(v.z); c.w = tf32f(v.w);
        ((float4*)g_xt)[j] = c;
    }
}

// ---------------------------------------------------------------------------
// 1) Luma + key bias, fused
// ---------------------------------------------------------------------------
__global__ void k_lumabias(const float* __restrict__ rgb, const float* __restrict__ alpha_p) {
    __shared__ float sy[NPIX];
    __shared__ float pli[2500];
    __shared__ float red[256];
    int b = blockIdx.x, t = threadIdx.x;
    const float* rp = rgb + (size_t)b * 3 * NPIX;
    float lmn = 1e30f, lmx = -1e30f;
#pragma unroll
    for (int k = 0; k < 9; k++) {
        int p = t + k * 256;
        float y = 0.299f * rp[p] + 0.587f * rp[NPIX + p] + 0.114f * rp[2 * NPIX + p];
        sy[p] = y;
        lmn = fminf(lmn, y); lmx = fmaxf(lmx, y);
    }
    red[t] = lmn; __syncthreads();
    for (int s = 128; s > 0; s >>= 1) { if (t < s) red[t] = fminf(red[t], red[t + s]); __syncthreads(); }
    float mn = red[0]; __syncthreads();
    red[t] = lmx; __syncthreads();
    for (int s = 128; s > 0; s >>= 1) { if (t < s) red[t] = fmaxf(red[t], red[t + s]); __syncthreads(); }
    float mx = red[0]; __syncthreads();
    float inv = 1.0f / (mx - mn + 1e-6f);

    for (int i = t; i < 2500; i += 256) pli[i] = 0.f;
    __syncthreads();
#pragma unroll
    for (int k = 0; k < 9; k++) {
        int p = t + k * 256;
        float ln = (sy[p] - mn) * inv;
        g_luma[b * NPIX + p] = ln;
        pli[(p / 48 + 1) * 50 + (p % 48) + 1] = 1.0f - ln;
    }
    __syncthreads();
    float lsum = 0.f;
#pragma unroll
    for (int k = 0; k < 9; k++) {
        int p = t + k * 256;
        int bi = (p / 48 + 1) * 50 + (p % 48) + 1;
        float s = pli[bi - 51] + pli[bi - 50] + pli[bi - 49]
                + pli[bi - 1]  + pli[bi]      + pli[bi + 1]
                + pli[bi + 49] + pli[bi + 50] + pli[bi + 51];
        s *= (1.0f / 9.0f);
        sy[p] = s; lsum += s;
    }
    red[t] = lsum; __syncthreads();
    for (int s = 128; s > 0; s >>= 1) { if (t < s) red[t] += red[t + s]; __syncthreads(); }
    float mean = red[0] * (1.0f / (float)NPIX);
    float a = *alpha_p;
#pragma unroll
    for (int k = 0; k < 9; k++) {
        int p = t + k * 256;
        g_biasE[b * NPIX + p] = a * (sy[p] - mean) * LOG2E;
    }
}

// ---------------------------------------------------------------------------
// 2) Conv1: luma[1ch] -> h1 padded [50x52] planes, 3x3 SAME, ReLU
// ---------------------------------------------------------------------------
__global__ void k_conv1(const float* __restrict__ w1, const float* __restrict__ b1) {
    __shared__ float pl[2500];
    int oc = blockIdx.x, b = blockIdx.y, t = threadIdx.x;
    for (int i = t; i < 2500; i += 256) pl[i] = 0.f;
    __syncthreads();
    const float* L = g_luma + b * NPIX;
#pragma unroll
    for (int k = 0; k < 9; k++) {
        int p = t + k * 256;
        pl[(p / 48 + 1) * 50 + (p % 48) + 1] = L[p];
    }
    __syncthreads();
    float w[9];
#pragma unroll
    for (int i = 0; i < 9; i++) w[i] = w1[oc * 9 + i];
    float bb = b1[oc];
    float* dst = g_h1p + ((size_t)(b * HID + oc)) * PH_PLANE;
    for (int i = t; i < PH_PLANE; i += 256) {
        int r = i / PH_COLS, c = i % PH_COLS;
        if (r == 0 || r == 49 || c == 0 || c >= 49) dst[i] = 0.f;
    }
#pragma unroll
    for (int k = 0; k < 9; k++) {
        int p = t + k * 256;
        int bi = (p / 48 + 1) * 50 + (p % 48) + 1;
        float s = bb
            + pl[bi - 51] * w[0] + pl[bi - 50] * w[1] + pl[bi - 49] * w[2]
            + pl[bi - 1]  * w[3] + pl[bi]      * w[4] + pl[bi + 1]  * w[5]
            + pl[bi + 49] * w[6] + pl[bi + 50] * w[7] + pl[bi + 51] * w[8];
        dst[(p / 48 + 1) * PH_COLS + (p % 48) + 1] = fmaxf(s, 0.f);
    }
}

// ---------------------------------------------------------------------------
// 3) Conv2 + ReLU + spatial mean (band partials). Padded h1, register
//    prefetch (no barriers in ic loop), 8 output channels per block.
//    grid (16 ocg, 4 b, 6 band), 96 thr (12x8).
// ---------------------------------------------------------------------------
__global__ __launch_bounds__(96) void k_conv2mean(const float* __restrict__ w2,
                                                  const float* __restrict__ b2) {
    __shared__ float wsm[128 * 72];   // [ic][tap][oc8]
    int ocg = blockIdx.x, b = blockIdx.y, band = blockIdx.z;
    int t = threadIdx.x;
    int ty = t / 12, tx = t % 12;

    for (int i = t; i < 128 * 72; i += 96) {
        int ic = i / 72, r = i % 72;
        int tap = r >> 3, oc = r & 7;
        wsm[i] = w2[(((ocg * 8 + oc) * 128) + ic) * 9 + tap];
    }
    __syncthreads();

    int row = band * 8 + ty;
    int col0 = tx * 4;
    const float* srcb = g_h1p + (size_t)b * HID * PH_PLANE;
    int off0 = row * PH_COLS + col0;

    float2 acc2[4][4];   // [px][oc-pair]
#pragma unroll
    for (int j = 0; j < 4; j++)
#pragma unroll
        for (int p = 0; p < 4; p++) acc2[j][p] = make_float2(0.f, 0.f);

    float4 ha[3]; float2 hb[3];
#pragma unroll
    for (int r = 0; r < 3; r++) {
        ha[r] = *(const float4*)&srcb[off0 + r * PH_COLS];
        hb[r] = *(const float2*)&srcb[off0 + r * PH_COLS + 4];
    }

    for (int ic = 0; ic < 128; ++ic) {
        float4 han[3]; float2 hbn[3];
        if (ic < 127) {
            const float* sn = srcb + (size_t)(ic + 1) * PH_PLANE;
#pragma unroll
            for (int r = 0; r < 3; r++) {
                han[r] = *(const float4*)&sn[off0 + r * PH_COLS];
                hbn[r] = *(const float2*)&sn[off0 + r * PH_COLS + 4];
            }
        }
        const float4* wv = (const float4*)&wsm[ic * 72];
#pragma unroll
        for (int r = 0; r < 3; r++) {
            float v[6] = { ha[r].x, ha[r].y, ha[r].z, ha[r].w, hb[r].x, hb[r].y };
#pragma unroll
            for (int tc = 0; tc < 3; tc++) {
                int tap = r * 3 + tc;
                float4 wa = wv[tap * 2];
                float4 wb = wv[tap * 2 + 1];
                float2 w01 = make_float2(wa.x, wa.y), w23 = make_float2(wa.z, wa.w);
                float2 w45 = make_float2(wb.x, wb.y), w67 = make_float2(wb.z, wb.w);
#pragma unroll
                for (int j = 0; j < 4; j++) {
                    float vv = v[j + tc];
                    float2 tt = make_float2(vv, vv);
                    acc2[j][0] = ffma2(tt, w01, acc2[j][0]);
                    acc2[j][1] = ffma2(tt, w23, acc2[j][1]);
                    acc2[j][2] = ffma2(tt, w45, acc2[j][2]);
                    acc2[j][3] = ffma2(tt, w67, acc2[j][3]);
                }
            }
        }
#pragma unroll
        for (int r = 0; r < 3; r++) { ha[r] = han[r]; hb[r] = hbn[r]; }
    }
    float prt[8];
#pragma unroll
    for (int oc = 0; oc < 8; oc++) prt[oc] = 0.f;
#pragma unroll
    for (int p = 0; p < 4; p++) {
        float b0 = b2[ocg * 8 + 2 * p], b1 = b2[ocg * 8 + 2 * p + 1];
#pragma unroll
        for (int j = 0; j < 4; j++) {
            prt[2 * p]     += fmaxf(acc2[j][p].x + b0, 0.f);
            prt[2 * p + 1] += fmaxf(acc2[j][p].y + b1, 0.f);
        }
    }
    __syncthreads();
    for (int oc = 0; oc < 8; oc++) {
        wsm[t] = prt[oc];
        __syncthreads();
        if (t < 32) {
            float v = wsm[t] + wsm[t + 32] + wsm[t + 64];
            v += __shfl_xor_sync(0xffffffffu, v, 16);
            v += __shfl_xor_sync(0xffffffffu, v, 8);
            v += __shfl_xor_sync(0xffffffffu, v, 4);
            v += __shfl_xor_sync(0xffffffffu, v, 2);
            v += __shfl_xor_sync(0xffffffffu, v, 1);
            if (t == 0) g_hmp[(band * BSZ + b) * HID + ocg * 8 + oc] = v * (1.0f / (float)NPIX);
        }
        __syncthreads();
    }
}

// ---------------------------------------------------------------------------
// 4) FiLM parameter GEMVs (sums 6 conv2 band partials)
// ---------------------------------------------------------------------------
struct FilmArgs { const float* w[6]; const float* b[6]; };

__global__ void k_film(FilmArgs fa) {
    int s = blockIdx.x, b = blockIdx.y, o = threadIdx.x;
    __shared__ float sh[HID];
    if (threadIdx.x < HID) {
        int h = threadIdx.x;
        float acc = 0.f;
#pragma unroll
        for (int bd = 0; bd < 6; bd++) acc += g_hmp[(bd * BSZ + b) * HID + h];
        sh[h] = acc;
    }
    __syncthreads();
    const float* W = fa.w[s] + o * HID;
    float acc = fa.b[s][o];
#pragma unroll 8
    for (int h = 0; h < HID; h++) acc += sh[h] * W[h];
    g_film[(b * 6 + s) * 256 + o] = acc;
}

// ---------------------------------------------------------------------------
// 5) QKV GEMM via tf32 mma (+ bias + FiLM)
// ---------------------------------------------------------------------------
#define AW_STRIDE 36
#define BX_STRIDE 72

__global__ __launch_bounds__(256) void k_qkv(const float* __restrict__ bq,
                                             const float* __restrict__ bk,
                                             const float* __restrict__ bv) {
    __shared__ float wsm[128 * AW_STRIDE];
    __shared__ float xsm[32 * BX_STRIDE];
    int ntb = blockIdx.x, mt = blockIdx.y, z = blockIdx.z;
    int pr = z >> 2, b = z & 3;
    int t = threadIdx.x, warp = t >> 5, lane = t & 31;
    int gid = lane >> 2, tig = lane & 3;
    int n0 = ntb * 64;

    const float* W = g_Wt + pr * 65536 + mt * 128 * 256;
    const float* xb = g_xt + (size_t)b * CCH * NPIX;

    float s[8][4];
#pragma unroll
    for (int i = 0; i < 8; i++)
#pragma unroll
        for (int j = 0; j < 4; j++) s[i][j] = 0.f;

    for (int kk = 0; kk < 256; kk += 32) {
        if (kk) __syncthreads();
#pragma unroll
        for (int j = 0; j < 4; j++) {
            int idx = t + j * 256;
            int o = idx >> 3, cg = idx & 7;
            *(float4*)&wsm[o * AW_STRIDE + cg * 4] = *(const float4*)&W[o * 256 + kk + cg * 4];
        }
#pragma unroll
        for (int j = 0; j < 2; j++) {
            int idx = t + j * 256;
            int c = idx >> 4, ng = idx & 15;
            *(float4*)&xsm[c * BX_STRIDE + ng * 4] =
                *(const float4*)&xb[(size_t)(kk + c) * NPIX + n0 + ng * 4];
        }
        __syncthreads();
#pragma unroll
        for (int ks = 0; ks < 4; ks++) {
            uint32_t a[4];
            int ab = (warp * 16 + gid) * AW_STRIDE + ks * 8 + tig;
            a[0] = __float_as_uint(wsm[ab]);
            a[1] = __float_as_uint(wsm[ab + 8 * AW_STRIDE]);
            a[2] = __float_as_uint(wsm[ab + 4]);
            a[3] = __float_as_uint(wsm[ab + 8 * AW_STRIDE + 4]);
#pragma unroll
            for (int nt = 0; nt < 8; nt++) {
                int bbx = (ks * 8 + tig) * BX_STRIDE + nt * 8 + gid;
                mma_tf32(s[nt], a, __float_as_uint(xsm[bbx]),
                         __float_as_uint(xsm[bbx + 4 * BX_STRIDE]));
            }
        }
    }
    int o0 = mt * 128 + warp * 16 + gid, o1 = o0 + 8;
    const float* fg  = g_film + (b * 6 + 2 * pr) * 256;
    const float* fb2 = g_film + (b * 6 + 2 * pr + 1) * 256;
    const float* bias = (pr == 0) ? bq : (pr == 1) ? bk : bv;
    float g0 = fg[o0], g1 = fg[o1], e0 = fb2[o0], e1 = fb2[o1];
    float i0 = bias[o0], i1 = bias[o1];
    int h0 = o0 >> 5, d0 = o0 & 31, h1 = o1 >> 5, d1 = o1 & 31;
    float* outb = g_qkv + (size_t)pr * PR_STRIDE + (size_t)b * B_STRIDE;
    bool rnd = (pr != 0);
#pragma unroll
    for (int nt = 0; nt < 8; nt++) {
        int n = n0 + nt * 8 + 2 * tig;
        float v00 = g0 * (s[nt][0] + i0) + e0;
        float v01 = g0 * (s[nt][1] + i0) + e0;
        float v10 = g1 * (s[nt][2] + i1) + e1;
        float v11 = g1 * (s[nt][3] + i1) + e1;
        if (rnd) { v00 = tf32f(v00); v01 = tf32f(v01); v10 = tf32f(v10); v11 = tf32f(v11); }
        outb[((size_t)h0 * NPIX + n) * 32 + d0]     = v00;
        outb[((size_t)h0 * NPIX + n + 1) * 32 + d0] = v01;
        outb[((size_t)h1 * NPIX + n) * 32 + d1]     = v10;
        outb[((size_t)h1 * NPIX + n + 1) * 32 + d1] = v11;
    }
}

// ---------------------------------------------------------------------------
// 6) Flash attention with tf32 mma, cp.async double-buffered K/V/bias.
// ---------------------------------------------------------------------------
#define KS_STRIDE 36
#define VS_STRIDE 40
#define PS_STRIDE 68
#define STAGE_F   (64 * KS_STRIDE + 64 * VS_STRIDE)     // 4864 floats
#define PSM_OFF   (2 * STAGE_F)                          // 9728
#define BSM_OFF   (PSM_OFF + 8 * 16 * PS_STRIDE)         // 18432
#define ATTN_SMEM ((BSM_OFF + 128) * 4)                  // 74240 B

__global__ __launch_bounds__(256) void k_attn() {
    extern __shared__ float smp[];
    float* psm = smp + PSM_OFF;

    int t = threadIdx.x;
    int warp = t >> 5, lane = t & 31;
    int gid = lane >> 2, tig = lane & 3;
    int bh = blockIdx.y;
    int b = bh >> 3;

    const float* Qb = g_qkv + (size_t)bh * BH_STRIDE;
    const float* Kb = g_qkv + (size_t)PR_STRIDE + (size_t)bh * BH_STRIDE;
    const float* Vb = g_qkv + (size_t)2 * PR_STRIDE + (size_t)bh * BH_STRIDE;
    const float* bE = g_biasE + b * NPIX;

    uint32_t smb = (uint32_t)__cvta_generic_to_shared(smp);

    int qr = blockIdx.x * 128 + warp * 16 + gid;

    uint32_t aq[4][4];
#pragma unroll
    for (int ks = 0; ks < 4; ks++) {
        aq[ks][0] = tf32c(Qb[(size_t)qr * 32 + ks * 8 + tig] * QSC);
        aq[ks][1] = tf32c(Qb[(size_t)(qr + 8) * 32 + ks * 8 + tig] * QSC);
        aq[ks][2] = tf32c(Qb[(size_t)qr * 32 + ks * 8 + tig + 4] * QSC);
        aq[ks][3] = tf32c(Qb[(size_t)(qr + 8) * 32 + ks * 8 + tig + 4] * QSC);
    }

    float o[4][4];
#pragma unroll
    for (int i = 0; i < 4; i++)
#pragma unroll
        for (int j = 0; j < 4; j++) o[i][j] = 0.f;
    float m0 = -1e30f, m1 = -1e30f, l0 = 0.f, l1 = 0.f;

    float* pw = psm + warp * 16 * PS_STRIDE;

    {
        const float4* Kg = (const float4*)Kb;
        const float4* Vg = (const float4*)Vb;
#pragma unroll
        for (int i = t; i < 512; i += 256) {
            int key = i >> 3, dq = i & 7;
            cpasync16(smb + (key * KS_STRIDE + dq * 4) * 4, Kg + i);
            cpasync16(smb + (64 * KS_STRIDE + key * VS_STRIDE + dq * 4) * 4, Vg + i);
        }
        if (t < 16) cpasync16(smb + (BSM_OFF + t * 4) * 4, bE + t * 4);
        CP_COMMIT();
        CP_WAIT0();
    }
    __syncthreads();

    for (int nk = 0; nk < 36; ++nk) {
        int cu = nk & 1, nx = cu ^ 1;
        if (nk < 35) {
            const float4* Kg = (const float4*)Kb + (nk + 1) * 512;
            const float4* Vg = (const float4*)Vb + (nk + 1) * 512;
            uint32_t ksu = smb + nx * STAGE_F * 4;
            uint32_t vsu = ksu + 64 * KS_STRIDE * 4;
#pragma unroll
            for (int i = t; i < 512; i += 256) {
                int key = i >> 3, dq = i & 7;
                cpasync16(ksu + (key * KS_STRIDE + dq * 4) * 4, Kg + i);
                cpasync16(vsu + (key * VS_STRIDE + dq * 4) * 4, Vg + i);
            }
            if (t < 16) cpasync16(smb + (BSM_OFF + nx * 64 + t * 4) * 4,
                                  bE + (nk + 1) * 64 + t * 4);
            CP_COMMIT();
        }

        const float* ksm = smp + cu * STAGE_F;
        const float* vsm = ksm + 64 * KS_STRIDE;
        const float* bsm = smp + BSM_OFF + cu * 64;

        float s[8][4];
#pragma unroll
        for (int nt = 0; nt < 8; nt++)
#pragma unroll
            for (int c = 0; c < 4; c++) s[nt][c] = 0.f;
#pragma unroll
        for (int ks = 0; ks < 4; ks++) {
#pragma unroll
            for (int nt = 0; nt < 8; nt++) {
                int kb = (nt * 8 + gid) * KS_STRIDE + ks * 8 + tig;
                uint32_t b0 = __float_as_uint(ksm[kb]);
                uint32_t b1 = __float_as_uint(ksm[kb + 4]);
                mma_tf32(s[nt], aq[ks], b0, b1);
            }
        }
        float mx0 = -1e30f, mx1 = -1e30f;
#pragma unroll
        for (int nt = 0; nt < 8; nt++) {
            float b0v = bsm[nt * 8 + 2 * tig];
            float b1v = bsm[nt * 8 + 2 * tig + 1];
            s[nt][0] += b0v; s[nt][1] += b1v;
            s[nt][2] += b0v; s[nt][3] += b1v;
            mx0 = fmaxf(mx0, fmaxf(s[nt][0], s[nt][1]));
            mx1 = fmaxf(mx1, fmaxf(s[nt][2], s[nt][3]));
        }
        mx0 = fmaxf(mx0, __shfl_xor_sync(0xffffffffu, mx0, 1));
        mx0 = fmaxf(mx0, __shfl_xor_sync(0xffffffffu, mx0, 2));
        mx1 = fmaxf(mx1, __shfl_xor_sync(0xffffffffu, mx1, 1));
        mx1 = fmaxf(mx1, __shfl_xor_sync(0xffffffffu, mx1, 2));

        float mn0 = fmaxf(m0, mx0), mn1 = fmaxf(m1, mx1);
        float c0 = ex2f(m0 - mn0), c1 = ex2f(m1 - mn1);
        m0 = mn0; m1 = mn1;

        float rs0 = 0.f, rs1 = 0.f;
#pragma unroll
        for (int nt = 0; nt < 8; nt++) {
            float p00 = ex2f(s[nt][0] - mn0);
            float p01 = ex2f(s[nt][1] - mn0);
            float p10 = ex2f(s[nt][2] - mn1);
            float p11 = ex2f(s[nt][3] - mn1);
            rs0 += p00 + p01; rs1 += p10 + p11;
            float2 lo, hi;
            lo.x = tf32f(p00); lo.y = tf32f(p01);
            hi.x = tf32f(p10); hi.y = tf32f(p11);
            *(float2*)&pw[gid * PS_STRIDE + nt * 8 + 2 * tig] = lo;
            *(float2*)&pw[(gid + 8) * PS_STRIDE + nt * 8 + 2 * tig] = hi;
        }
        rs0 += __shfl_xor_sync(0xffffffffu, rs0, 1);
        rs0 += __shfl_xor_sync(0xffffffffu, rs0, 2);
        rs1 += __shfl_xor_sync(0xffffffffu, rs1, 1);
        rs1 += __shfl_xor_sync(0xffffffffu, rs1, 2);
        l0 = l0 * c0 + rs0;
        l1 = l1 * c1 + rs1;
#pragma unroll
        for (int nt = 0; nt < 4; nt++) {
            o[nt][0] *= c0; o[nt][1] *= c0;
            o[nt][2] *= c1; o[nt][3] *= c1;
        }
        __syncwarp();

#pragma unroll
        for (int ks = 0; ks < 8; ks++) {
            uint32_t a[4];
            a[0] = __float_as_uint(pw[gid * PS_STRIDE + ks * 8 + tig]);
            a[1] = __float_as_uint(pw[(gid + 8) * PS_STRIDE + ks * 8 + tig]);
            a[2] = __float_as_uint(pw[gid * PS_STRIDE + ks * 8 + tig + 4]);
            a[3] = __float_as_uint(pw[(gid + 8) * PS_STRIDE + ks * 8 + tig + 4]);
#pragma unroll
            for (int nt = 0; nt < 4; nt++) {
                int vb = (ks * 8 + tig) * VS_STRIDE + nt * 8 + gid;
                uint32_t b0 = __float_as_uint(vsm[vb]);
                uint32_t b1 = __float_as_uint(vsm[vb + 4 * VS_STRIDE]);
                mma_tf32(o[nt], a, b0, b1);
            }
        }
        if (nk < 35) CP_WAIT0();
        __syncthreads();
    }

    float i0 = 1.0f / l0, i1 = 1.0f / l1;
    float* AO = g_ao + (size_t)bh * BH_STRIDE;
#pragma unroll
    for (int nt = 0; nt < 4; nt++) {
        float2 lo = make_float2(tf32f(o[nt][0] * i0), tf32f(o[nt][1] * i0));
        float2 hi = make_float2(tf32f(o[nt][2] * i1), tf32f(o[nt][3] * i1));
        *(float2*)&AO[(size_t)qr * 32 + nt * 8 + 2 * tig] = lo;
        *(float2*)&AO[(size_t)(qr + 8) * 32 + nt * 8 + 2 * tig] = hi;
    }
}

// ---------------------------------------------------------------------------
// 7) Output projection via tf32 mma
// ---------------------------------------------------------------------------
__global__ __launch_bounds__(256) void k_proj(const float* __restrict__ bproj,
                                              float* __restrict__ out) {
    __shared__ float wsm[128 * AW_STRIDE];
    __shared__ float bsm2[32 * BX_STRIDE];
    int ntb = blockIdx.x, mt = blockIdx.y, b = blockIdx.z;
    int t = threadIdx.x, warp = t >> 5, lane = t & 31;
    int gid = lane >> 2, tig = lane & 3;
    int n0 = ntb * 64;

    const float* W = g_Wt + 3 * 65536 + mt * 128 * 256;
    const float* AOb = g_ao + (size_t)b * B_STRIDE;

    float s[8][4];
#pragma unroll
    for (int i = 0; i < 8; i++)
#pragma unroll
        for (int j = 0; j < 4; j++) s[i][j] = 0.f;

    for (int kk = 0; kk < 256; kk += 32) {
        if (kk) __syncthreads();
#pragma unroll
        for (int j = 0; j < 4; j++) {
            int idx = t + j * 256;
            int o = idx >> 3, cg = idx & 7;
            *(float4*)&wsm[o * AW_STRIDE + cg * 4] = *(const float4*)&W[o * 256 + kk + cg * 4];
        }
#pragma unroll
        for (int j = 0; j < 8; j++) {
            int idx = t + j * 256;
            int c = idx >> 6, ng = idx & 63;
            int o = kk + c;
            bsm2[c * BX_STRIDE + ng] =
                AOb[((size_t)(o >> 5) * NPIX + n0 + ng) * 32 + (o & 31)];
        }
        __syncthreads();
#pragma unroll
        for (int ks = 0; ks < 4; ks++) {
            uint32_t a[4];
            int ab = (warp * 16 + gid) * AW_STRIDE + ks * 8 + tig;
            a[0] = __float_as_uint(wsm[ab]);
            a[1] = __float_as_uint(wsm[ab + 8 * AW_STRIDE]);
            a[2] = __float_as_uint(wsm[ab + 4]);
            a[3] = __float_as_uint(wsm[ab + 8 * AW_STRIDE + 4]);
#pragma unroll
            for (int nt = 0; nt < 8; nt++) {
                int bbx = (ks * 8 + tig) * BX_STRIDE + nt * 8 + gid;
                mma_tf32(s[nt], a, __float_as_uint(bsm2[bbx]),
                         __float_as_uint(bsm2[bbx + 4 * BX_STRIDE]));
            }
        }
    }
    int o0 = mt * 128 + warp * 16 + gid, o1 = o0 + 8;
    float bp0 = bproj[o0], bp1 = bproj[o1];
#pragma unroll
    for (int nt = 0; nt < 8; nt++) {
        int n = n0 + nt * 8 + 2 * tig;
        *(float2*)&out[((size_t)(b * 256 + o0)) * NPIX + n] =
            make_float2(s[nt][0] + bp0, s[nt][1] + bp0);
        *(float2*)&out[((size_t)(b * 256 + o1)) * NPIX + n] =
            make_float2(s[nt][2] + bp1, s[nt][3] + bp1);
    }
}

// ---------------------------------------------------------------------------
// launch (single stream — R14's fork regressed)
// ---------------------------------------------------------------------------
extern "C" void kernel_launch(void* const* d_in, const int* in_sizes, int n_in,
                              void* d_out, int out_size) {
    const float* x     = (const float*)d_in[0];
    const float* rgb   = (const float*)d_in[1];
    const float* wq    = (const float*)d_in[2];
    const float* bq    = (const float*)d_in[3];
    const float* wk    = (const float*)d_in[4];
    const float* bk    = (const float*)d_in[5];
    const float* wv    = (const float*)d_in[6];
    const float* bv    = (const float*)d_in[7];
    const float* wproj = (const float*)d_in[8];
    const float* bproj = (const float*)d_in[9];
    const float* c1w   = (const float*)d_in[10];
    const float* c1b   = (const float*)d_in[11];
    const float* c2w   = (const float*)d_in[12];
    const float* c2b   = (const float*)d_in[13];
    const float* alpha = (const float*)d_in[26];

    FilmArgs fa;
    fa.w[0] = (const float*)d_in[14]; fa.b[0] = (const float*)d_in[15];
    fa.w[1] = (const float*)d_in[16]; fa.b[1] = (const float*)d_in[17];
    fa.w[2] = (const float*)d_in[18]; fa.b[2] = (const float*)d_in[19];
    fa.w[3] = (const float*)d_in[20]; fa.b[3] = (const float*)d_in[21];
    fa.w[4] = (const float*)d_in[22]; fa.b[4] = (const float*)d_in[23];
    fa.w[5] = (const float*)d_in[24]; fa.b[5] = (const float*)d_in[25];

    static bool attr_done = false;
    if (!attr_done) {
        cudaFuncSetAttribute(k_attn, cudaFuncAttributeMaxDynamicSharedMemorySize, ATTN_SMEM);
        attr_done = true;
    }

    k_prep<<<2560, 256>>>(wq, wk, wv, wproj, x);
    k_lumabias<<<BSZ, 256>>>(rgb, alpha);
    k_conv1<<<dim3(HID, BSZ), 256>>>(c1w, c1b);
    k_conv2mean<<<dim3(16, BSZ, 6), 96>>>(c2w, c2b);
    k_film<<<dim3(6, BSZ), 256>>>(fa);
    k_qkv<<<dim3(36, 2, 12), 256>>>(bq, bk, bv);
    k_attn<<<dim3(18, 32), 256, ATTN_SMEM>>>();
    k_proj<<<dim3(36, 2, 4), 256>>>(bproj, (float*)d_out);
}

// round 16
// speedup vs baseline: 1.0697x; 1.0575x over previous
#include <cuda_runtime.h>
#include <cstdint>

// ---------------------------------------------------------------------------
// Problem constants
// ---------------------------------------------------------------------------
#define BSZ    4
#define CCH    256
#define HH     48
#define WW     48
#define NPIX   2304          // 48*48
#define HEADS  8
#define DH     32
#define INNER  256
#define HID    128
#define LOG2E  1.4426950408889634f
#define QSC    (0.17677669529663687f * 1.4426950408889634f)

// padded h1 plane: 50 rows x 52 cols (px (r,c) at (r+1, c+1))
#define PH_ROWS 50
#define PH_COLS 52
#define PH_PLANE (PH_ROWS * PH_COLS)   // 2600

// ---------------------------------------------------------------------------
// Scratch
// ---------------------------------------------------------------------------
__device__ float g_Wt[4 * 256 * 256];          // tf32 patterns: wq,wk,wv,wproj
__device__ float g_luma[BSZ * NPIX];
__device__ float g_biasE[BSZ * NPIX];
__device__ float g_h1p[BSZ * HID * PH_PLANE]; // zero-padded conv1 output
__device__ float g_hmp[6 * BSZ * HID];         // 6 band partials
__device__ float g_film[BSZ * 6 * 256];
__device__ float g_qkv[3 * BSZ * HEADS * NPIX * DH];   // [pr][b][h][n][d]; K,V tf32
__device__ float g_ao[BSZ * HEADS * NPIX * DH];        // tf32-rounded

#define PR_STRIDE (BSZ * HEADS * NPIX * DH)
#define BH_STRIDE (NPIX * DH)
#define B_STRIDE  (HEADS * NPIX * DH)

// ---------------------------------------------------------------------------
// Helpers
// ---------------------------------------------------------------------------
static __device__ __forceinline__ float2 ffma2(float2 a, float2 b, float2 c) {
    float2 d;
    asm("fma.rn.f32x2 %0, %1, %2, %3;"
        : "=l"(reinterpret_cast<unsigned long long&>(d))
        : "l"(reinterpret_cast<unsigned long long&>(a)),
          "l"(reinterpret_cast<unsigned long long&>(b)),
          "l"(reinterpret_cast<unsigned long long&>(c)));
    return d;
}
static __device__ __forceinline__ float ex2f(float x) {
    float r;
    asm("ex2.approx.f32 %0, %1;" : "=f"(r) : "f"(x));
    return r;
}
static __device__ __forceinline__ uint32_t tf32c(float f) {
    uint32_t u;
    asm("cvt.rna.tf32.f32 %0, %1;" : "=r"(u) : "f"(f));
    return u;
}
static __device__ __forceinline__ float tf32f(float f) {
    return __uint_as_float(tf32c(f));
}
static __device__ __forceinline__ float4 tf32f4(float4 v) {
    float4 c;
    c.x = tf32f(v.x); c.y = tf32f(v.y); c.z = tf32f(v.z); c.w = tf32f(v.w);
    return c;
}
static __device__ __forceinline__ void mma_tf32(float* d, const uint32_t* a,
                                                uint32_t b0, uint32_t b1) {
    asm("mma.sync.aligned.m16n8k8.row.col.f32.tf32.tf32.f32 "
        "{%0,%1,%2,%3}, {%4,%5,%6,%7}, {%8,%9}, {%0,%1,%2,%3};"
        : "+f"(d[0]), "+f"(d[1]), "+f"(d[2]), "+f"(d[3])
        : "r"(a[0]), "r"(a[1]), "r"(a[2]), "r"(a[3]), "r"(b0), "r"(b1));
}
static __device__ __forceinline__ void cpasync16(uint32_t smem_addr, const void* gptr) {
    asm volatile("cp.async.cg.shared.global [%0], [%1], 16;"
                 :: "r"(smem_addr), "l"(gptr));
}
#define CP_COMMIT() asm volatile("cp.async.commit_group;")
#define CP_WAIT0()  asm volatile("cp.async.wait_group 0;" ::: "memory")

// ---------------------------------------------------------------------------
// 0) Prep: convert weights to tf32 bit patterns (x converted in k_qkv).
// ---------------------------------------------------------------------------
__global__ void k_prep(const float* __restrict__ wq, const float* __restrict__ wk,
                       const float* __restrict__ wv, const float* __restrict__ wp) {
    int i = blockIdx.x * 256 + threadIdx.x;   // < 65536 float4
    int slot = i >> 14, j = i & 16383;
    const float* src = (slot == 0) ? wq : (slot == 1) ? wk : (slot == 2) ? wv : wp;
    ((float4*)g_Wt)[slot * 16384 + j] = tf32f4(((const float4*)src)[j]);
}

// ---------------------------------------------------------------------------
// 1) Luma + key bias, fused
// ---------------------------------------------------------------------------
__global__ void k_lumabias(const float* __restrict__ rgb, const float* __restrict__ alpha_p) {
    __shared__ float sy[NPIX];
    __shared__ float pli[2500];
    __shared__ float red[256];
    int b = blockIdx.x, t = threadIdx.x;
    const float* rp = rgb + (size_t)b * 3 * NPIX;
    float lmn = 1e30f, lmx = -1e30f;
#pragma unroll
    for (int k = 0; k < 9; k++) {
        int p = t + k * 256;
        float y = 0.299f * rp[p] + 0.587f * rp[NPIX + p] + 0.114f * rp[2 * NPIX + p];
        sy[p] = y;
        lmn = fminf(lmn, y); lmx = fmaxf(lmx, y);
    }
    red[t] = lmn; __syncthreads();
    for (int s = 128; s > 0; s >>= 1) { if (t < s) red[t] = fminf(red[t], red[t + s]); __syncthreads(); }
    float mn = red[0]; __syncthreads();
    red[t] = lmx; __syncthreads();
    for (int s = 128; s > 0; s >>= 1) { if (t < s) red[t] = fmaxf(red[t], red[t + s]); __syncthreads(); }
    float mx = red[0]; __syncthreads();
    float inv = 1.0f / (mx - mn + 1e-6f);

    for (int i = t; i < 2500; i += 256) pli[i] = 0.f;
    __syncthreads();
#pragma unroll
    for (int k = 0; k < 9; k++) {
        int p = t + k * 256;
        float ln = (sy[p] - mn) * inv;
        g_luma[b * NPIX + p] = ln;
        pli[(p / 48 + 1) * 50 + (p % 48) + 1] = 1.0f - ln;
    }
    __syncthreads();
    float lsum = 0.f;
#pragma unroll
    for (int k = 0; k < 9; k++) {
        int p = t + k * 256;
        int bi = (p / 48 + 1) * 50 + (p % 48) + 1;
        float s = pli[bi - 51] + pli[bi - 50] + pli[bi - 49]
                + pli[bi - 1]  + pli[bi]      + pli[bi + 1]
                + pli[bi + 49] + pli[bi + 50] + pli[bi + 51];
        s *= (1.0f / 9.0f);
        sy[p] = s; lsum += s;
    }
    red[t] = lsum; __syncthreads();
    for (int s = 128; s > 0; s >>= 1) { if (t < s) red[t] += red[t + s]; __syncthreads(); }
    float mean = red[0] * (1.0f / (float)NPIX);
    float a = *alpha_p;
#pragma unroll
    for (int k = 0; k < 9; k++) {
        int p = t + k * 256;
        g_biasE[b * NPIX + p] = a * (sy[p] - mean) * LOG2E;
    }
}

// ---------------------------------------------------------------------------
// 2) Conv1: luma[1ch] -> h1 padded [50x52] planes, 3x3 SAME, ReLU
// ---------------------------------------------------------------------------
__global__ void k_conv1(const float* __restrict__ w1, const float* __restrict__ b1) {
    __shared__ float pl[2500];
    int oc = blockIdx.x, b = blockIdx.y, t = threadIdx.x;
    for (int i = t; i < 2500; i += 256) pl[i] = 0.f;
    __syncthreads();
    const float* L = g_luma + b * NPIX;
#pragma unroll
    for (int k = 0; k < 9; k++) {
        int p = t + k * 256;
        pl[(p / 48 + 1) * 50 + (p % 48) + 1] = L[p];
    }
    __syncthreads();
    float w[9];
#pragma unroll
    for (int i = 0; i < 9; i++) w[i] = w1[oc * 9 + i];
    float bb = b1[oc];
    float* dst = g_h1p + ((size_t)(b * HID + oc)) * PH_PLANE;
    for (int i = t; i < PH_PLANE; i += 256) {
        int r = i / PH_COLS, c = i % PH_COLS;
        if (r == 0 || r == 49 || c == 0 || c >= 49) dst[i] = 0.f;
    }
#pragma unroll
    for (int k = 0; k < 9; k++) {
        int p = t + k * 256;
        int bi = (p / 48 + 1) * 50 + (p % 48) + 1;
        float s = bb
            + pl[bi - 51] * w[0] + pl[bi - 50] * w[1] + pl[bi - 49] * w[2]
            + pl[bi - 1]  * w[3] + pl[bi]      * w[4] + pl[bi + 1]  * w[5]
            + pl[bi + 49] * w[6] + pl[bi + 50] * w[7] + pl[bi + 51] * w[8];
        dst[(p / 48 + 1) * PH_COLS + (p % 48) + 1] = fmaxf(s, 0.f);
    }
}

// ---------------------------------------------------------------------------
// 3) Conv2 + ReLU + spatial mean (band partials). Padded h1: no shfl, no
//    bounds checks, register prefetch. grid (32 ocg, 4 b, 6 band), 96 thr.
//    (R12/R13 configuration — local optimum, do not touch.)
// ---------------------------------------------------------------------------
__global__ __launch_bounds__(96) void k_conv2mean(const float* __restrict__ w2,
                                                  const float* __restrict__ b2) {
    __shared__ float wsm[128 * 36];   // [ic][tap][oc4]
    int ocg = blockIdx.x, b = blockIdx.y, band = blockIdx.z;
    int t = threadIdx.x;
    int ty = t / 12, tx = t % 12;

    for (int i = t; i < 128 * 36; i += 96) {
        int ic = i / 36, r = i % 36;
        int tap = r >> 2, oc = r & 3;
        wsm[i] = w2[(((ocg * 4 + oc) * 128) + ic) * 9 + tap];
    }
    __syncthreads();

    int row = band * 8 + ty;
    int col0 = tx * 4;
    const float* srcb = g_h1p + (size_t)b * HID * PH_PLANE;
    int off0 = row * PH_COLS + col0;

    float2 acc2[4][2];
#pragma unroll
    for (int j = 0; j < 4; j++) { acc2[j][0] = make_float2(0.f, 0.f); acc2[j][1] = make_float2(0.f, 0.f); }

    float4 ha[3]; float2 hb[3];
#pragma unroll
    for (int r = 0; r < 3; r++) {
        ha[r] = *(const float4*)&srcb[off0 + r * PH_COLS];
        hb[r] = *(const float2*)&srcb[off0 + r * PH_COLS + 4];
    }

    for (int ic = 0; ic < 128; ++ic) {
        float4 han[3]; float2 hbn[3];
        if (ic < 127) {
            const float* sn = srcb + (size_t)(ic + 1) * PH_PLANE;
#pragma unroll
            for (int r = 0; r < 3; r++) {
                han[r] = *(const float4*)&sn[off0 + r * PH_COLS];
                hbn[r] = *(const float2*)&sn[off0 + r * PH_COLS + 4];
            }
        }
        const float4* wv = (const float4*)&wsm[ic * 36];
#pragma unroll
        for (int r = 0; r < 3; r++) {
            float v[6] = { ha[r].x, ha[r].y, ha[r].z, ha[r].w, hb[r].x, hb[r].y };
#pragma unroll
            for (int tc = 0; tc < 3; tc++) {
                float4 w4 = wv[r * 3 + tc];
                float2 wlo = make_float2(w4.x, w4.y), whi = make_float2(w4.z, w4.w);
#pragma unroll
                for (int j = 0; j < 4; j++) {
                    float vv = v[j + tc];
                    float2 tt = make_float2(vv, vv);
                    acc2[j][0] = ffma2(tt, wlo, acc2[j][0]);
                    acc2[j][1] = ffma2(tt, whi, acc2[j][1]);
                }
            }
        }
#pragma unroll
        for (int r = 0; r < 3; r++) { ha[r] = han[r]; hb[r] = hbn[r]; }
    }
    float bb[4] = { b2[ocg * 4 + 0], b2[ocg * 4 + 1], b2[ocg * 4 + 2], b2[ocg * 4 + 3] };
    float prt[4];
#pragma unroll
    for (int oc = 0; oc < 4; oc++) prt[oc] = 0.f;
#pragma unroll
    for (int j = 0; j < 4; j++) {
        prt[0] += fmaxf(acc2[j][0].x + bb[0], 0.f);
        prt[1] += fmaxf(acc2[j][0].y + bb[1], 0.f);
        prt[2] += fmaxf(acc2[j][1].x + bb[2], 0.f);
        prt[3] += fmaxf(acc2[j][1].y + bb[3], 0.f);
    }
    __syncthreads();
    for (int oc = 0; oc < 4; oc++) {
        wsm[t] = prt[oc];
        __syncthreads();
        if (t < 32) {
            float v = wsm[t] + wsm[t + 32] + wsm[t + 64];
            v += __shfl_xor_sync(0xffffffffu, v, 16);
            v += __shfl_xor_sync(0xffffffffu, v, 8);
            v += __shfl_xor_sync(0xffffffffu, v, 4);
            v += __shfl_xor_sync(0xffffffffu, v, 2);
            v += __shfl_xor_sync(0xffffffffu, v, 1);
            if (t == 0) g_hmp[(band * BSZ + b) * HID + ocg * 4 + oc] = v * (1.0f / (float)NPIX);
        }
        __syncthreads();
    }
}

// ---------------------------------------------------------------------------
// 4) FiLM parameter GEMVs (sums 6 conv2 band partials)
// ---------------------------------------------------------------------------
struct FilmArgs { const float* w[6]; const float* b[6]; };

__global__ void k_film(FilmArgs fa) {
    int s = blockIdx.x, b = blockIdx.y, o = threadIdx.x;
    __shared__ float sh[HID];
    if (threadIdx.x < HID) {
        int h = threadIdx.x;
        float acc = 0.f;
#pragma unroll
        for (int bd = 0; bd < 6; bd++) acc += g_hmp[(bd * BSZ + b) * HID + h];
        sh[h] = acc;
    }
    __syncthreads();
    const float* W = fa.w[s] + o * HID;
    float acc = fa.b[s][o];
#pragma unroll 8
    for (int h = 0; h < HID; h++) acc += sh[h] * W[h];
    g_film[(b * 6 + s) * 256 + o] = acc;
}

// ---------------------------------------------------------------------------
// 5) QKV GEMM via tf32 mma (+ bias + FiLM); x converted to tf32 in-register
//    during staging (bit-identical to the old g_xt path).
// ---------------------------------------------------------------------------
#define AW_STRIDE 36
#define BX_STRIDE 72

__global__ __launch_bounds__(256) void k_qkv(const float* __restrict__ x,
                                             const float* __restrict__ bq,
                                             const float* __restrict__ bk,
                                             const float* __restrict__ bv) {
    __shared__ float wsm[128 * AW_STRIDE];
    __shared__ float xsm[32 * BX_STRIDE];
    int ntb = blockIdx.x, mt = blockIdx.y, z = blockIdx.z;
    int pr = z >> 2, b = z & 3;
    int t = threadIdx.x, warp = t >> 5, lane = t & 31;
    int gid = lane >> 2, tig = lane & 3;
    int n0 = ntb * 64;

    const float* W = g_Wt + pr * 65536 + mt * 128 * 256;
    const float* xb = x + (size_t)b * CCH * NPIX;

    float s[8][4];
#pragma unroll
    for (int i = 0; i < 8; i++)
#pragma unroll
        for (int j = 0; j < 4; j++) s[i][j] = 0.f;

    for (int kk = 0; kk < 256; kk += 32) {
        if (kk) __syncthreads();
#pragma unroll
        for (int j = 0; j < 4; j++) {
            int idx = t + j * 256;
            int o = idx >> 3, cg = idx & 7;
            *(float4*)&wsm[o * AW_STRIDE + cg * 4] = *(const float4*)&W[o * 256 + kk + cg * 4];
        }
#pragma unroll
        for (int j = 0; j < 2; j++) {
            int idx = t + j * 256;
            int c = idx >> 4, ng = idx & 15;
            *(float4*)&xsm[c * BX_STRIDE + ng * 4] =
                tf32f4(*(const float4*)&xb[(size_t)(kk + c) * NPIX + n0 + ng * 4]);
        }
        __syncthreads();
#pragma unroll
        for (int ks = 0; ks < 4; ks++) {
            uint32_t a[4];
            int ab = (warp * 16 + gid) * AW_STRIDE + ks * 8 + tig;
            a[0] = __float_as_uint(wsm[ab]);
            a[1] = __float_as_uint(wsm[ab + 8 * AW_STRIDE]);
            a[2] = __float_as_uint(wsm[ab + 4]);
            a[3] = __float_as_uint(wsm[ab + 8 * AW_STRIDE + 4]);
#pragma unroll
            for (int nt = 0; nt < 8; nt++) {
                int bbx = (ks * 8 + tig) * BX_STRIDE + nt * 8 + gid;
                mma_tf32(s[nt], a, __float_as_uint(xsm[bbx]),
                         __float_as_uint(xsm[bbx + 4 * BX_STRIDE]));
            }
        }
    }
    int o0 = mt * 128 + warp * 16 + gid, o1 = o0 + 8;
    const float* fg  = g_film + (b * 6 + 2 * pr) * 256;
    const float* fb2 = g_film + (b * 6 + 2 * pr + 1) * 256;
    const float* bias = (pr == 0) ? bq : (pr == 1) ? bk : bv;
    float g0 = fg[o0], g1 = fg[o1], e0 = fb2[o0], e1 = fb2[o1];
    float i0 = bias[o0], i1 = bias[o1];
    int h0 = o0 >> 5, d0 = o0 & 31, h1 = o1 >> 5, d1 = o1 & 31;
    float* outb = g_qkv + (size_t)pr * PR_STRIDE + (size_t)b * B_STRIDE;
    bool rnd = (pr != 0);
#pragma unroll
    for (int nt = 0; nt < 8; nt++) {
        int n = n0 + nt * 8 + 2 * tig;
        float v00 = g0 * (s[nt][0] + i0) + e0;
        float v01 = g0 * (s[nt][1] + i0) + e0;
        float v10 = g1 * (s[nt][2] + i1) + e1;
        float v11 = g1 * (s[nt][3] + i1) + e1;
        if (rnd) { v00 = tf32f(v00); v01 = tf32f(v01); v10 = tf32f(v10); v11 = tf32f(v11); }
        outb[((size_t)h0 * NPIX + n) * 32 + d0]     = v00;
        outb[((size_t)h0 * NPIX + n + 1) * 32 + d0] = v01;
        outb[((size_t)h1 * NPIX + n) * 32 + d1]     = v10;
        outb[((size_t)h1 * NPIX + n + 1) * 32 + d1] = v11;
    }
}

// ---------------------------------------------------------------------------
// 6) Flash attention with tf32 mma, cp.async double-buffered K/V/bias.
// ---------------------------------------------------------------------------
#define KS_STRIDE 36
#define VS_STRIDE 40
#define PS_STRIDE 68
#define STAGE_F   (64 * KS_STRIDE + 64 * VS_STRIDE)     // 4864 floats
#define PSM_OFF   (2 * STAGE_F)                          // 9728
#define BSM_OFF   (PSM_OFF + 8 * 16 * PS_STRIDE)         // 18432
#define ATTN_SMEM ((BSM_OFF + 128) * 4)                  // 74240 B

__global__ __launch_bounds__(256) void k_attn() {
    extern __shared__ float smp[];
    float* psm = smp + PSM_OFF;

    int t = threadIdx.x;
    int warp = t >> 5, lane = t & 31;
    int gid = lane >> 2, tig = lane & 3;
    int bh = blockIdx.y;
    int b = bh >> 3;

    const float* Qb = g_qkv + (size_t)bh * BH_STRIDE;
    const float* Kb = g_qkv + (size_t)PR_STRIDE + (size_t)bh * BH_STRIDE;
    const float* Vb = g_qkv + (size_t)2 * PR_STRIDE + (size_t)bh * BH_STRIDE;
    const float* bE = g_biasE + b * NPIX;

    uint32_t smb = (uint32_t)__cvta_generic_to_shared(smp);

    int qr = blockIdx.x * 128 + warp * 16 + gid;

    uint32_t aq[4][4];
#pragma unroll
    for (int ks = 0; ks < 4; ks++) {
        aq[ks][0] = tf32c(Qb[(size_t)qr * 32 + ks * 8 + tig] * QSC);
        aq[ks][1] = tf32c(Qb[(size_t)(qr + 8) * 32 + ks * 8 + tig] * QSC);
        aq[ks][2] = tf32c(Qb[(size_t)qr * 32 + ks * 8 + tig + 4] * QSC);
        aq[ks][3] = tf32c(Qb[(size_t)(qr + 8) * 32 + ks * 8 + tig + 4] * QSC);
    }

    float o[4][4];
#pragma unroll
    for (int i = 0; i < 4; i++)
#pragma unroll
        for (int j = 0; j < 4; j++) o[i][j] = 0.f;
    float m0 = -1e30f, m1 = -1e30f, l0 = 0.f, l1 = 0.f;

    float* pw = psm + warp * 16 * PS_STRIDE;

    {
        const float4* Kg = (const float4*)Kb;
        const float4* Vg = (const float4*)Vb;
#pragma unroll
        for (int i = t; i < 512; i += 256) {
            int key = i >> 3, dq = i & 7;
            cpasync16(smb + (key * KS_STRIDE + dq * 4) * 4, Kg + i);
            cpasync16(smb + (64 * KS_STRIDE + key * VS_STRIDE + dq * 4) * 4, Vg + i);
        }
        if (t < 16) cpasync16(smb + (BSM_OFF + t * 4) * 4, bE + t * 4);
        CP_COMMIT();
        CP_WAIT0();
    }
    __syncthreads();

    for (int nk = 0; nk < 36; ++nk) {
        int cu = nk & 1, nx = cu ^ 1;
        if (nk < 35) {
            const float4* Kg = (const float4*)Kb + (nk + 1) * 512;
            const float4* Vg = (const float4*)Vb + (nk + 1) * 512;
            uint32_t ksu = smb + nx * STAGE_F * 4;
            uint32_t vsu = ksu + 64 * KS_STRIDE * 4;
#pragma unroll
            for (int i = t; i < 512; i += 256) {
                int key = i >> 3, dq = i & 7;
                cpasync16(ksu + (key * KS_STRIDE + dq * 4) * 4, Kg + i);
                cpasync16(vsu + (key * VS_STRIDE + dq * 4) * 4, Vg + i);
            }
            if (t < 16) cpasync16(smb + (BSM_OFF + nx * 64 + t * 4) * 4,
                                  bE + (nk + 1) * 64 + t * 4);
            CP_COMMIT();
        }

        const float* ksm = smp + cu * STAGE_F;
        const float* vsm = ksm + 64 * KS_STRIDE;
        const float* bsm = smp + BSM_OFF + cu * 64;

        float s[8][4];
#pragma unroll
        for (int nt = 0; nt < 8; nt++)
#pragma unroll
            for (int c = 0; c < 4; c++) s[nt][c] = 0.f;
#pragma unroll
        for (int ks = 0; ks < 4; ks++) {
#pragma unroll
            for (int nt = 0; nt < 8; nt++) {
                int kb = (nt * 8 + gid) * KS_STRIDE + ks * 8 + tig;
                uint32_t b0 = __float_as_uint(ksm[kb]);
                uint32_t b1 = __float_as_uint(ksm[kb + 4]);
                mma_tf32(s[nt], aq[ks], b0, b1);
            }
        }
        float mx0 = -1e30f, mx1 = -1e30f;
#pragma unroll
        for (int nt = 0; nt < 8; nt++) {
            float b0v = bsm[nt * 8 + 2 * tig];
            float b1v = bsm[nt * 8 + 2 * tig + 1];
            s[nt][0] += b0v; s[nt][1] += b1v;
            s[nt][2] += b0v; s[nt][3] += b1v;
            mx0 = fmaxf(mx0, fmaxf(s[nt][0], s[nt][1]));
            mx1 = fmaxf(mx1, fmaxf(s[nt][2], s[nt][3]));
        }
        mx0 = fmaxf(mx0, __shfl_xor_sync(0xffffffffu, mx0, 1));
        mx0 = fmaxf(mx0, __shfl_xor_sync(0xffffffffu, mx0, 2));
        mx1 = fmaxf(mx1, __shfl_xor_sync(0xffffffffu, mx1, 1));
        mx1 = fmaxf(mx1, __shfl_xor_sync(0xffffffffu, mx1, 2));

        float mn0 = fmaxf(m0, mx0), mn1 = fmaxf(m1, mx1);
        float c0 = ex2f(m0 - mn0), c1 = ex2f(m1 - mn1);
        m0 = mn0; m1 = mn1;

        float rs0 = 0.f, rs1 = 0.f;
#pragma unroll
        for (int nt = 0; nt < 8; nt++) {
            float p00 = ex2f(s[nt][0] - mn0);
            float p01 = ex2f(s[nt][1] - mn0);
            float p10 = ex2f(s[nt][2] - mn1);
            float p11 = ex2f(s[nt][3] - mn1);
            rs0 += p00 + p01; rs1 += p10 + p11;
            float2 lo, hi;
            lo.x = tf32f(p00); lo.y = tf32f(p01);
            hi.x = tf32f(p10); hi.y = tf32f(p11);
            *(float2*)&pw[gid * PS_STRIDE + nt * 8 + 2 * tig] = lo;
            *(float2*)&pw[(gid + 8) * PS_STRIDE + nt * 8 + 2 * tig] = hi;
        }
        rs0 += __shfl_xor_sync(0xffffffffu, rs0, 1);
        rs0 += __shfl_xor_sync(0xffffffffu, rs0, 2);
        rs1 += __shfl_xor_sync(0xffffffffu, rs1, 1);
        rs1 += __shfl_xor_sync(0xffffffffu, rs1, 2);
        l0 = l0 * c0 + rs0;
        l1 = l1 * c1 + rs1;
#pragma unroll
        for (int nt = 0; nt < 4; nt++) {
            o[nt][0] *= c0; o[nt][1] *= c0;
            o[nt][2] *= c1; o[nt][3] *= c1;
        }
        __syncwarp();

#pragma unroll
        for (int ks = 0; ks < 8; ks++) {
            uint32_t a[4];
            a[0] = __float_as_uint(pw[gid * PS_STRIDE + ks * 8 + tig]);
            a[1] = __float_as_uint(pw[(gid + 8) * PS_STRIDE + ks * 8 + tig]);
            a[2] = __float_as_uint(pw[gid * PS_STRIDE + ks * 8 + tig + 4]);
            a[3] = __float_as_uint(pw[(gid + 8) * PS_STRIDE + ks * 8 + tig + 4]);
#pragma unroll
            for (int nt = 0; nt < 4; nt++) {
                int vb = (ks * 8 + tig) * VS_STRIDE + nt * 8 + gid;
                uint32_t b0 = __float_as_uint(vsm[vb]);
                uint32_t b1 = __float_as_uint(vsm[vb + 4 * VS_STRIDE]);
                mma_tf32(o[nt], a, b0, b1);
            }
        }
        if (nk < 35) CP_WAIT0();
        __syncthreads();
    }

    float i0 = 1.0f / l0, i1 = 1.0f / l1;
    float* AO = g_ao + (size_t)bh * BH_STRIDE;
#pragma unroll
    for (int nt = 0; nt < 4; nt++) {
        float2 lo = make_float2(tf32f(o[nt][0] * i0), tf32f(o[nt][1] * i0));
        float2 hi = make_float2(tf32f(o[nt][2] * i1), tf32f(o[nt][3] * i1));
        *(float2*)&AO[(size_t)qr * 32 + nt * 8 + 2 * tig] = lo;
        *(float2*)&AO[(size_t)(qr + 8) * 32 + nt * 8 + 2 * tig] = hi;
    }
}

// ---------------------------------------------------------------------------
// 7) Output projection via tf32 mma
// ---------------------------------------------------------------------------
__global__ __launch_bounds__(256) void k_proj(const float* __restrict__ bproj,
                                              float* __restrict__ out) {
    __shared__ float wsm[128 * AW_STRIDE];
    __shared__ float bsm2[32 * BX_STRIDE];
    int ntb = blockIdx.x, mt = blockIdx.y, b = blockIdx.z;
    int t = threadIdx.x, warp = t >> 5, lane = t & 31;
    int gid = lane >> 2, tig = lane & 3;
    int n0 = ntb * 64;

    const float* W = g_Wt + 3 * 65536 + mt * 128 * 256;
    const float* AOb = g_ao + (size_t)b * B_STRIDE;

    float s[8][4];
#pragma unroll
    for (int i = 0; i < 8; i++)
#pragma unroll
        for (int j = 0; j < 4; j++) s[i][j] = 0.f;

    for (int kk = 0; kk < 256; kk += 32) {
        if (kk) __syncthreads();
#pragma unroll
        for (int j = 0; j < 4; j++) {
            int idx = t + j * 256;
            int o = idx >> 3, cg = idx & 7;
            *(float4*)&wsm[o * AW_STRIDE + cg * 4] = *(const float4*)&W[o * 256 + kk + cg * 4];
        }
#pragma unroll
        for (int j = 0; j < 8; j++) {
            int idx = t + j * 256;
            int c = idx >> 6, ng = idx & 63;
            int o = kk + c;
            bsm2[c * BX_STRIDE + ng] =
                AOb[((size_t)(o >> 5) * NPIX + n0 + ng) * 32 + (o & 31)];
        }
        __syncthreads();
#pragma unroll
        for (int ks = 0; ks < 4; ks++) {
            uint32_t a[4];
            int ab = (warp * 16 + gid) * AW_STRIDE + ks * 8 + tig;
            a[0] = __float_as_uint(wsm[ab]);
            a[1] = __float_as_uint(wsm[ab + 8 * AW_STRIDE]);
            a[2] = __float_as_uint(wsm[ab + 4]);
            a[3] = __float_as_uint(wsm[ab + 8 * AW_STRIDE + 4]);
#pragma unroll
            for (int nt = 0; nt < 8; nt++) {
                int bbx = (ks * 8 + tig) * BX_STRIDE + nt * 8 + gid;
                mma_tf32(s[nt], a, __float_as_uint(bsm2[bbx]),
                         __float_as_uint(bsm2[bbx + 4 * BX_STRIDE]));
            }
        }
    }
    int o0 = mt * 128 + warp * 16 + gid, o1 = o0 + 8;
    float bp0 = bproj[o0], bp1 = bproj[o1];
#pragma unroll
    for (int nt = 0; nt < 8; nt++) {
        int n = n0 + nt * 8 + 2 * tig;
        *(float2*)&out[((size_t)(b * 256 + o0)) * NPIX + n] =
            make_float2(s[nt][0] + bp0, s[nt][1] + bp0);
        *(float2*)&out[((size_t)(b * 256 + o1)) * NPIX + n] =
            make_float2(s[nt][2] + bp1, s[nt][3] + bp1);
    }
}

// ---------------------------------------------------------------------------
// launch
// ---------------------------------------------------------------------------
extern "C" void kernel_launch(void* const* d_in, const int* in_sizes, int n_in,
                              void* d_out, int out_size) {
    const float* x     = (const float*)d_in[0];
    const float* rgb   = (const float*)d_in[1];
    const float* wq    = (const float*)d_in[2];
    const float* bq    = (const float*)d_in[3];
    const float* wk    = (const float*)d_in[4];
    const float* bk    = (const float*)d_in[5];
    const float* wv    = (const float*)d_in[6];
    const float* bv    = (const float*)d_in[7];
    const float* wproj = (const float*)d_in[8];
    const float* bproj = (const float*)d_in[9];
    const float* c1w   = (const float*)d_in[10];
    const float* c1b   = (const float*)d_in[11];
    const float* c2w   = (const float*)d_in[12];
    const float* c2b   = (const float*)d_in[13];
    const float* alpha = (const float*)d_in[26];

    FilmArgs fa;
    fa.w[0] = (const float*)d_in[14]; fa.b[0] = (const float*)d_in[15];
    fa.w[1] = (const float*)d_in[16]; fa.b[1] = (const float*)d_in[17];
    fa.w[2] = (const float*)d_in[18]; fa.b[2] = (const float*)d_in[19];
    fa.w[3] = (const float*)d_in[20]; fa.b[3] = (const float*)d_in[21];
    fa.w[4] = (const float*)d_in[22]; fa.b[4] = (const float*)d_in[23];
    fa.w[5] = (const float*)d_in[24]; fa.b[5] = (const float*)d_in[25];

    static bool attr_done = false;
    if (!attr_done) {
        cudaFuncSetAttribute(k_attn, cudaFuncAttributeMaxDynamicSharedMemorySize, ATTN_SMEM);
        attr_done = true;
    }

    k_prep<<<256, 256>>>(wq, wk, wv, wproj);
    k_lumabias<<<BSZ, 256>>>(rgb, alpha);
    k_conv1<<<dim3(HID, BSZ), 256>>>(c1w, c1b);
    k_conv2mean<<<dim3(32, BSZ, 6), 96>>>(c2w, c2b);
    k_film<<<dim3(6, BSZ), 256>>>(fa);
    k_qkv<<<dim3(36, 2, 12), 256>>>(x, bq, bk, bv);
    k_attn<<<dim3(18, 32), 256, ATTN_SMEM>>>();
    k_proj<<<dim3(36, 2, 4), 256>>>(bproj, (float*)d_out);
}

// round 17
// speedup vs baseline: 1.3594x; 1.2709x over previous
#include <cuda_runtime.h>
#include <cuda_fp16.h>
#include <cstdint>

// ---------------------------------------------------------------------------
// Problem constants
// ---------------------------------------------------------------------------
#define BSZ    4
#define CCH    256
#define HH     48
#define WW     48
#define NPIX   2304          // 48*48
#define HEADS  8
#define DH     32
#define INNER  256
#define HID    128
#define LOG2E  1.4426950408889634f
#define QSC    (0.17677669529663687f * 1.4426950408889634f)

// padded h1 plane: 50 rows x 52 cols (px (r,c) at (r+1, c+1))
#define PH_ROWS 50
#define PH_COLS 52
#define PH_PLANE (PH_ROWS * PH_COLS)   // 2600

// ---------------------------------------------------------------------------
// Scratch
// ---------------------------------------------------------------------------
__device__ float  g_Wt[4 * 256 * 256];         // tf32 patterns: wq,wk,wv,wproj
__device__ float  g_luma[BSZ * NPIX];
__device__ float  g_biasE[BSZ * NPIX];
__device__ float  g_h1p[BSZ * HID * PH_PLANE];
__device__ float  g_hmp[6 * BSZ * HID];
__device__ float  g_film[BSZ * 6 * 256];
__device__ __half g_qh[BSZ * HEADS * NPIX * DH];   // Q (QSC folded), fp16
__device__ __half g_kh[BSZ * HEADS * NPIX * DH];   // K fp16
__device__ __half g_vh[BSZ * HEADS * NPIX * DH];   // V fp16
__device__ float  g_ao[BSZ * HEADS * NPIX * DH];   // tf32-rounded

#define BH_STRIDE (NPIX * DH)
#define B_STRIDE  (HEADS * NPIX * DH)

// ---------------------------------------------------------------------------
// Helpers
// ---------------------------------------------------------------------------
static __device__ __forceinline__ float2 ffma2(float2 a, float2 b, float2 c) {
    float2 d;
    asm("fma.rn.f32x2 %0, %1, %2, %3;"
        : "=l"(reinterpret_cast<unsigned long long&>(d))
        : "l"(reinterpret_cast<unsigned long long&>(a)),
          "l"(reinterpret_cast<unsigned long long&>(b)),
          "l"(reinterpret_cast<unsigned long long&>(c)));
    return d;
}
static __device__ __forceinline__ float ex2f(float x) {
    float r;
    asm("ex2.approx.f32 %0, %1;" : "=f"(r) : "f"(x));
    return r;
}
static __device__ __forceinline__ uint32_t tf32c(float f) {
    uint32_t u;
    asm("cvt.rna.tf32.f32 %0, %1;" : "=r"(u) : "f"(f));
    return u;
}
static __device__ __forceinline__ float tf32f(float f) {
    return __uint_as_float(tf32c(f));
}
static __device__ __forceinline__ float4 tf32f4(float4 v) {
    float4 c;
    c.x = tf32f(v.x); c.y = tf32f(v.y); c.z = tf32f(v.z); c.w = tf32f(v.w);
    return c;
}
static __device__ __forceinline__ void mma_tf32(float* d, const uint32_t* a,
                                                uint32_t b0, uint32_t b1) {
    asm("mma.sync.aligned.m16n8k8.row.col.f32.tf32.tf32.f32 "
        "{%0,%1,%2,%3}, {%4,%5,%6,%7}, {%8,%9}, {%0,%1,%2,%3};"
        : "+f"(d[0]), "+f"(d[1]), "+f"(d[2]), "+f"(d[3])
        : "r"(a[0]), "r"(a[1]), "r"(a[2]), "r"(a[3]), "r"(b0), "r"(b1));
}
static __device__ __forceinline__ void mma_f16(float* d, const uint32_t* a,
                                               uint32_t b0, uint32_t b1) {
    asm("mma.sync.aligned.m16n8k16.row.col.f32.f16.f16.f32 "
        "{%0,%1,%2,%3}, {%4,%5,%6,%7}, {%8,%9}, {%0,%1,%2,%3};"
        : "+f"(d[0]), "+f"(d[1]), "+f"(d[2]), "+f"(d[3])
        : "r"(a[0]), "r"(a[1]), "r"(a[2]), "r"(a[3]), "r"(b0), "r"(b1));
}
static __device__ __forceinline__ void ldsm2(uint32_t& b0, uint32_t& b1, uint32_t addr) {
    asm volatile("ldmatrix.sync.aligned.m8n8.x2.shared.b16 {%0,%1}, [%2];"
                 : "=r"(b0), "=r"(b1) : "r"(addr));
}
static __device__ __forceinline__ void ldsm2t(uint32_t& b0, uint32_t& b1, uint32_t addr) {
    asm volatile("ldmatrix.sync.aligned.m8n8.x2.trans.shared.b16 {%0,%1}, [%2];"
                 : "=r"(b0), "=r"(b1) : "r"(addr));
}
static __device__ __forceinline__ void cpasync16(uint32_t smem_addr, const void* gptr) {
    asm volatile("cp.async.cg.shared.global [%0], [%1], 16;"
                 :: "r"(smem_addr), "l"(gptr));
}
#define CP_COMMIT() asm volatile("cp.async.commit_group;")
#define CP_WAIT0()  asm volatile("cp.async.wait_group 0;" ::: "memory")

// ---------------------------------------------------------------------------
// 0) Prep: convert weights to tf32 bit patterns (x converted in k_qkv).
// ---------------------------------------------------------------------------
__global__ void k_prep(const float* __restrict__ wq, const float* __restrict__ wk,
                       const float* __restrict__ wv, const float* __restrict__ wp) {
    int i = blockIdx.x * 256 + threadIdx.x;   // < 65536 float4
    int slot = i >> 14, j = i & 16383;
    const float* src = (slot == 0) ? wq : (slot == 1) ? wk : (slot == 2) ? wv : wp;
    ((float4*)g_Wt)[slot * 16384 + j] = tf32f4(((const float4*)src)[j]);
}

// ---------------------------------------------------------------------------
// 1) Luma + key bias, fused
// ---------------------------------------------------------------------------
__global__ void k_lumabias(const float* __restrict__ rgb, const float* __restrict__ alpha_p) {
    __shared__ float sy[NPIX];
    __shared__ float pli[2500];
    __shared__ float red[256];
    int b = blockIdx.x, t = threadIdx.x;
    const float* rp = rgb + (size_t)b * 3 * NPIX;
    float lmn = 1e30f, lmx = -1e30f;
#pragma unroll
    for (int k = 0; k < 9; k++) {
        int p = t + k * 256;
        float y = 0.299f * rp[p] + 0.587f * rp[NPIX + p] + 0.114f * rp[2 * NPIX + p];
        sy[p] = y;
        lmn = fminf(lmn, y); lmx = fmaxf(lmx, y);
    }
    red[t] = lmn; __syncthreads();
    for (int s = 128; s > 0; s >>= 1) { if (t < s) red[t] = fminf(red[t], red[t + s]); __syncthreads(); }
    float mn = red[0]; __syncthreads();
    red[t] = lmx; __syncthreads();
    for (int s = 128; s > 0; s >>= 1) { if (t < s) red[t] = fmaxf(red[t], red[t + s]); __syncthreads(); }
    float mx = red[0]; __syncthreads();
    float inv = 1.0f / (mx - mn + 1e-6f);

    for (int i = t; i < 2500; i += 256) pli[i] = 0.f;
    __syncthreads();
#pragma unroll
    for (int k = 0; k < 9; k++) {
        int p = t + k * 256;
        float ln = (sy[p] - mn) * inv;
        g_luma[b * NPIX + p] = ln;
        pli[(p / 48 + 1) * 50 + (p % 48) + 1] = 1.0f - ln;
    }
    __syncthreads();
    float lsum = 0.f;
#pragma unroll
    for (int k = 0; k < 9; k++) {
        int p = t + k * 256;
        int bi = (p / 48 + 1) * 50 + (p % 48) + 1;
        float s = pli[bi - 51] + pli[bi - 50] + pli[bi - 49]
                + pli[bi - 1]  + pli[bi]      + pli[bi + 1]
                + pli[bi + 49] + pli[bi + 50] + pli[bi + 51];
        s *= (1.0f / 9.0f);
        sy[p] = s; lsum += s;
    }
    red[t] = lsum; __syncthreads();
    for (int s = 128; s > 0; s >>= 1) { if (t < s) red[t] += red[t + s]; __syncthreads(); }
    float mean = red[0] * (1.0f / (float)NPIX);
    float a = *alpha_p;
#pragma unroll
    for (int k = 0; k < 9; k++) {
        int p = t + k * 256;
        g_biasE[b * NPIX + p] = a * (sy[p] - mean) * LOG2E;
    }
}

// ---------------------------------------------------------------------------
// 2) Conv1: luma[1ch] -> h1 padded [50x52] planes, 3x3 SAME, ReLU
// ---------------------------------------------------------------------------
__global__ void k_conv1(const float* __restrict__ w1, const float* __restrict__ b1) {
    __shared__ float pl[2500];
    int oc = blockIdx.x, b = blockIdx.y, t = threadIdx.x;
    for (int i = t; i < 2500; i += 256) pl[i] = 0.f;
    __syncthreads();
    const float* L = g_luma + b * NPIX;
#pragma unroll
    for (int k = 0; k < 9; k++) {
        int p = t + k * 256;
        pl[(p / 48 + 1) * 50 + (p % 48) + 1] = L[p];
    }
    __syncthreads();
    float w[9];
#pragma unroll
    for (int i = 0; i < 9; i++) w[i] = w1[oc * 9 + i];
    float bb = b1[oc];
    float* dst = g_h1p + ((size_t)(b * HID + oc)) * PH_PLANE;
    for (int i = t; i < PH_PLANE; i += 256) {
        int r = i / PH_COLS, c = i % PH_COLS;
        if (r == 0 || r == 49 || c == 0 || c >= 49) dst[i] = 0.f;
    }
#pragma unroll
    for (int k = 0; k < 9; k++) {
        int p = t + k * 256;
        int bi = (p / 48 + 1) * 50 + (p % 48) + 1;
        float s = bb
            + pl[bi - 51] * w[0] + pl[bi - 50] * w[1] + pl[bi - 49] * w[2]
            + pl[bi - 1]  * w[3] + pl[bi]      * w[4] + pl[bi + 1]  * w[5]
            + pl[bi + 49] * w[6] + pl[bi + 50] * w[7] + pl[bi + 51] * w[8];
        dst[(p / 48 + 1) * PH_COLS + (p % 48) + 1] = fmaxf(s, 0.f);
    }
}

// ---------------------------------------------------------------------------
// 3) Conv2 + ReLU + spatial mean (band partials). R12/R13 config — frozen.
// ---------------------------------------------------------------------------
__global__ __launch_bounds__(96) void k_conv2mean(const float* __restrict__ w2,
                                                  const float* __restrict__ b2) {
    __shared__ float wsm[128 * 36];   // [ic][tap][oc4]
    int ocg = blockIdx.x, b = blockIdx.y, band = blockIdx.z;
    int t = threadIdx.x;
    int ty = t / 12, tx = t % 12;

    for (int i = t; i < 128 * 36; i += 96) {
        int ic = i / 36, r = i % 36;
        int tap = r >> 2, oc = r & 3;
        wsm[i] = w2[(((ocg * 4 + oc) * 128) + ic) * 9 + tap];
    }
    __syncthreads();

    int row = band * 8 + ty;
    int col0 = tx * 4;
    const float* srcb = g_h1p + (size_t)b * HID * PH_PLANE;
    int off0 = row * PH_COLS + col0;

    float2 acc2[4][2];
#pragma unroll
    for (int j = 0; j < 4; j++) { acc2[j][0] = make_float2(0.f, 0.f); acc2[j][1] = make_float2(0.f, 0.f); }

    float4 ha[3]; float2 hb[3];
#pragma unroll
    for (int r = 0; r < 3; r++) {
        ha[r] = *(const float4*)&srcb[off0 + r * PH_COLS];
        hb[r] = *(const float2*)&srcb[off0 + r * PH_COLS + 4];
    }

    for (int ic = 0; ic < 128; ++ic) {
        float4 han[3]; float2 hbn[3];
        if (ic < 127) {
            const float* sn = srcb + (size_t)(ic + 1) * PH_PLANE;
#pragma unroll
            for (int r = 0; r < 3; r++) {
                han[r] = *(const float4*)&sn[off0 + r * PH_COLS];
                hbn[r] = *(const float2*)&sn[off0 + r * PH_COLS + 4];
            }
        }
        const float4* wv = (const float4*)&wsm[ic * 36];
#pragma unroll
        for (int r = 0; r < 3; r++) {
            float v[6] = { ha[r].x, ha[r].y, ha[r].z, ha[r].w, hb[r].x, hb[r].y };
#pragma unroll
            for (int tc = 0; tc < 3; tc++) {
                float4 w4 = wv[r * 3 + tc];
                float2 wlo = make_float2(w4.x, w4.y), whi = make_float2(w4.z, w4.w);
#pragma unroll
                for (int j = 0; j < 4; j++) {
                    float vv = v[j + tc];
                    float2 tt = make_float2(vv, vv);
                    acc2[j][0] = ffma2(tt, wlo, acc2[j][0]);
                    acc2[j][1] = ffma2(tt, whi, acc2[j][1]);
                }
            }
        }
#pragma unroll
        for (int r = 0; r < 3; r++) { ha[r] = han[r]; hb[r] = hbn[r]; }
    }
    float bb[4] = { b2[ocg * 4 + 0], b2[ocg * 4 + 1], b2[ocg * 4 + 2], b2[ocg * 4 + 3] };
    float prt[4];
#pragma unroll
    for (int oc = 0; oc < 4; oc++) prt[oc] = 0.f;
#pragma unroll
    for (int j = 0; j < 4; j++) {
        prt[0] += fmaxf(acc2[j][0].x + bb[0], 0.f);
        prt[1] += fmaxf(acc2[j][0].y + bb[1], 0.f);
        prt[2] += fmaxf(acc2[j][1].x + bb[2], 0.f);
        prt[3] += fmaxf(acc2[j][1].y + bb[3], 0.f);
    }
    __syncthreads();
    for (int oc = 0; oc < 4; oc++) {
        wsm[t] = prt[oc];
        __syncthreads();
        if (t < 32) {
            float v = wsm[t] + wsm[t + 32] + wsm[t + 64];
            v += __shfl_xor_sync(0xffffffffu, v, 16);
            v += __shfl_xor_sync(0xffffffffu, v, 8);
            v += __shfl_xor_sync(0xffffffffu, v, 4);
            v += __shfl_xor_sync(0xffffffffu, v, 2);
            v += __shfl_xor_sync(0xffffffffu, v, 1);
            if (t == 0) g_hmp[(band * BSZ + b) * HID + ocg * 4 + oc] = v * (1.0f / (float)NPIX);
        }
        __syncthreads();
    }
}

// ---------------------------------------------------------------------------
// 4) FiLM parameter GEMVs (sums 6 conv2 band partials)
// ---------------------------------------------------------------------------
struct FilmArgs { const float* w[6]; const float* b[6]; };

__global__ void k_film(FilmArgs fa) {
    int s = blockIdx.x, b = blockIdx.y, o = threadIdx.x;
    __shared__ float sh[HID];
    if (threadIdx.x < HID) {
        int h = threadIdx.x;
        float acc = 0.f;
#pragma unroll
        for (int bd = 0; bd < 6; bd++) acc += g_hmp[(bd * BSZ + b) * HID + h];
        sh[h] = acc;
    }
    __syncthreads();
    const float* W = fa.w[s] + o * HID;
    float acc = fa.b[s][o];
#pragma unroll 8
    for (int h = 0; h < HID; h++) acc += sh[h] * W[h];
    g_film[(b * 6 + s) * 256 + o] = acc;
}

// ---------------------------------------------------------------------------
// 5) QKV GEMM via tf32 mma (+ bias + FiLM); outputs fp16 Q/K/V (QSC folded
//    into Q). fp16 mantissa == tf32 mantissa -> precision unchanged.
// ---------------------------------------------------------------------------
#define AW_STRIDE 36
#define BX_STRIDE 72

__global__ __launch_bounds__(256) void k_qkv(const float* __restrict__ x,
                                             const float* __restrict__ bq,
                                             const float* __restrict__ bk,
                                             const float* __restrict__ bv) {
    __shared__ float wsm[128 * AW_STRIDE];
    __shared__ float xsm[32 * BX_STRIDE];
    int ntb = blockIdx.x, mt = blockIdx.y, z = blockIdx.z;
    int pr = z >> 2, b = z & 3;
    int t = threadIdx.x, warp = t >> 5, lane = t & 31;
    int gid = lane >> 2, tig = lane & 3;
    int n0 = ntb * 64;

    const float* W = g_Wt + pr * 65536 + mt * 128 * 256;
    const float* xb = x + (size_t)b * CCH * NPIX;

    float s[8][4];
#pragma unroll
    for (int i = 0; i < 8; i++)
#pragma unroll
        for (int j = 0; j < 4; j++) s[i][j] = 0.f;

    for (int kk = 0; kk < 256; kk += 32) {
        if (kk) __syncthreads();
#pragma unroll
        for (int j = 0; j < 4; j++) {
            int idx = t + j * 256;
            int o = idx >> 3, cg = idx & 7;
            *(float4*)&wsm[o * AW_STRIDE + cg * 4] = *(const float4*)&W[o * 256 + kk + cg * 4];
        }
#pragma unroll
        for (int j = 0; j < 2; j++) {
            int idx = t + j * 256;
            int c = idx >> 4, ng = idx & 15;
            *(float4*)&xsm[c * BX_STRIDE + ng * 4] =
                tf32f4(*(const float4*)&xb[(size_t)(kk + c) * NPIX + n0 + ng * 4]);
        }
        __syncthreads();
#pragma unroll
        for (int ks = 0; ks < 4; ks++) {
            uint32_t a[4];
            int ab = (warp * 16 + gid) * AW_STRIDE + ks * 8 + tig;
            a[0] = __float_as_uint(wsm[ab]);
            a[1] = __float_as_uint(wsm[ab + 8 * AW_STRIDE]);
            a[2] = __float_as_uint(wsm[ab + 4]);
            a[3] = __float_as_uint(wsm[ab + 8 * AW_STRIDE + 4]);
#pragma unroll
            for (int nt = 0; nt < 8; nt++) {
                int bbx = (ks * 8 + tig) * BX_STRIDE + nt * 8 + gid;
                mma_tf32(s[nt], a, __float_as_uint(xsm[bbx]),
                         __float_as_uint(xsm[bbx + 4 * BX_STRIDE]));
            }
        }
    }
    int o0 = mt * 128 + warp * 16 + gid, o1 = o0 + 8;
    const float* fg  = g_film + (b * 6 + 2 * pr) * 256;
    const float* fb2 = g_film + (b * 6 + 2 * pr + 1) * 256;
    const float* bias = (pr == 0) ? bq : (pr == 1) ? bk : bv;
    float g0 = fg[o0], g1 = fg[o1], e0 = fb2[o0], e1 = fb2[o1];
    float i0 = bias[o0], i1 = bias[o1];
    int h0 = o0 >> 5, d0 = o0 & 31, h1 = o1 >> 5, d1 = o1 & 31;
    __half* outh = ((pr == 0) ? g_qh : (pr == 1) ? g_kh : g_vh) + (size_t)b * B_STRIDE;
    float qs = (pr == 0) ? QSC : 1.0f;
#pragma unroll
    for (int nt = 0; nt < 8; nt++) {
        int n = n0 + nt * 8 + 2 * tig;
        float v00 = (g0 * (s[nt][0] + i0) + e0) * qs;
        float v01 = (g0 * (s[nt][1] + i0) + e0) * qs;
        float v10 = (g1 * (s[nt][2] + i1) + e1) * qs;
        float v11 = (g1 * (s[nt][3] + i1) + e1) * qs;
        outh[((size_t)h0 * NPIX + n) * 32 + d0]     = __float2half_rn(v00);
        outh[((size_t)h0 * NPIX + n + 1) * 32 + d0] = __float2half_rn(v01);
        outh[((size_t)h1 * NPIX + n) * 32 + d1]     = __float2half_rn(v10);
        outh[((size_t)h1 * NPIX + n + 1) * 32 + d1] = __float2half_rn(v11);
    }
}

// ---------------------------------------------------------------------------
// 6) Flash attention, fp16 m16n8k16 mma (fp32 accum), cp.async double-buffer.
//    smem (halves): stage0 K[0,2560) V[2560,5120); stage1 [5120,10240);
//    pw [10240, 27648); bias floats at byte 55296.
// ---------------------------------------------------------------------------
#define KS_H     40                       // halves per key row (80B, 16B-aligned)
#define STAGE_H  5120                     // K+V per stage, halves
#define PW_OFF   10240
#define PS_H     136                      // pw stride (halves) -> conflict-free
#define BIAS_B   55296                    // byte offset of bias floats
#define ATTN_SMEM (BIAS_B + 512)

__global__ __launch_bounds__(256) void k_attn() {
    extern __shared__ __align__(16) char smraw[];
    __half* hsm = (__half*)smraw;
    float* bsf = (float*)(smraw + BIAS_B);

    int t = threadIdx.x;
    int warp = t >> 5, lane = t & 31;
    int gid = lane >> 2, tig = lane & 3;
    int la = lane & 15;
    int bh = blockIdx.y;
    int b = bh >> 3;

    const __half* Qh = g_qh + (size_t)bh * BH_STRIDE;
    const __half* Kh = g_kh + (size_t)bh * BH_STRIDE;
    const __half* Vh = g_vh + (size_t)bh * BH_STRIDE;
    const float* bE = g_biasE + b * NPIX;

    uint32_t smb = (uint32_t)__cvta_generic_to_shared(hsm);
    __half* pw = hsm + PW_OFF + warp * 16 * PS_H;

    int qr = blockIdx.x * 128 + warp * 16 + gid;

    // Q fragments (A of m16n8k16): half2 pairs along d
    uint32_t aq[2][4];
#pragma unroll
    for (int ks = 0; ks < 2; ks++) {
        aq[ks][0] = *(const uint32_t*)(Qh + (size_t)qr * 32 + ks * 16 + 2 * tig);
        aq[ks][1] = *(const uint32_t*)(Qh + (size_t)(qr + 8) * 32 + ks * 16 + 2 * tig);
        aq[ks][2] = *(const uint32_t*)(Qh + (size_t)qr * 32 + ks * 16 + 8 + 2 * tig);
        aq[ks][3] = *(const uint32_t*)(Qh + (size_t)(qr + 8) * 32 + ks * 16 + 8 + 2 * tig);
    }

    float o[4][4];
#pragma unroll
    for (int i = 0; i < 4; i++)
#pragma unroll
        for (int j = 0; j < 4; j++) o[i][j] = 0.f;
    float m0 = -1e30f, m1 = -1e30f, l0 = 0.f, l1 = 0.f;

    // prologue: stage tile 0
    {
        int key = t >> 2, dq = t & 3;
        cpasync16(smb + (key * KS_H + dq * 8) * 2, Kh + (size_t)key * 32 + dq * 8);
        cpasync16(smb + (2560 + key * KS_H + dq * 8) * 2, Vh + (size_t)key * 32 + dq * 8);
        if (t < 16) cpasync16(smb + BIAS_B + t * 16, bE + t * 4);
        CP_COMMIT();
        CP_WAIT0();
    }
    __syncthreads();

    for (int nk = 0; nk < 36; ++nk) {
        int cu = nk & 1, nx = cu ^ 1;
        if (nk < 35) {
            int key = t >> 2, dq = t & 3;
            const __half* Kg = Kh + (size_t)(nk + 1) * 64 * 32;
            const __half* Vg = Vh + (size_t)(nk + 1) * 64 * 32;
            cpasync16(smb + (nx * STAGE_H + key * KS_H + dq * 8) * 2, Kg + (size_t)key * 32 + dq * 8);
            cpasync16(smb + (nx * STAGE_H + 2560 + key * KS_H + dq * 8) * 2, Vg + (size_t)key * 32 + dq * 8);
            if (t < 16) cpasync16(smb + BIAS_B + nx * 256 + t * 16, bE + (nk + 1) * 64 + t * 4);
            CP_COMMIT();
        }

        uint32_t kbase = smb + cu * STAGE_H * 2;
        uint32_t vbase = kbase + 2560 * 2;
        const float* bsm = bsf + cu * 64;

        // S = Q K^T : B = K [key][d] rows, plain ldmatrix (col-major B)
        float s[8][4];
#pragma unroll
        for (int nt = 0; nt < 8; nt++)
#pragma unroll
            for (int c = 0; c < 4; c++) s[nt][c] = 0.f;
#pragma unroll
        for (int ks = 0; ks < 2; ks++) {
#pragma unroll
            for (int nt = 0; nt < 8; nt++) {
                uint32_t b0, b1;
                uint32_t addr = kbase + ((nt * 8 + (la & 7)) * KS_H + ks * 16 + (la >> 3) * 8) * 2;
                ldsm2(b0, b1, addr);
                mma_f16(s[nt], aq[ks], b0, b1);
            }
        }
        float mx0 = -1e30f, mx1 = -1e30f;
#pragma unroll
        for (int nt = 0; nt < 8; nt++) {
            float b0v = bsm[nt * 8 + 2 * tig];
            float b1v = bsm[nt * 8 + 2 * tig + 1];
            s[nt][0] += b0v; s[nt][1] += b1v;
            s[nt][2] += b0v; s[nt][3] += b1v;
            mx0 = fmaxf(mx0, fmaxf(s[nt][0], s[nt][1]));
            mx1 = fmaxf(mx1, fmaxf(s[nt][2], s[nt][3]));
        }
        mx0 = fmaxf(mx0, __shfl_xor_sync(0xffffffffu, mx0, 1));
        mx0 = fmaxf(mx0, __shfl_xor_sync(0xffffffffu, mx0, 2));
        mx1 = fmaxf(mx1, __shfl_xor_sync(0xffffffffu, mx1, 1));
        mx1 = fmaxf(mx1, __shfl_xor_sync(0xffffffffu, mx1, 2));

        float mn0 = fmaxf(m0, mx0), mn1 = fmaxf(m1, mx1);
        float c0 = ex2f(m0 - mn0), c1 = ex2f(m1 - mn1);
        m0 = mn0; m1 = mn1;

        float rs0 = 0.f, rs1 = 0.f;
#pragma unroll
        for (int nt = 0; nt < 8; nt++) {
            float p00 = ex2f(s[nt][0] - mn0);
            float p01 = ex2f(s[nt][1] - mn0);
            float p10 = ex2f(s[nt][2] - mn1);
            float p11 = ex2f(s[nt][3] - mn1);
            rs0 += p00 + p01; rs1 += p10 + p11;
            *(__half2*)&pw[gid * PS_H + nt * 8 + 2 * tig] = __floats2half2_rn(p00, p01);
            *(__half2*)&pw[(gid + 8) * PS_H + nt * 8 + 2 * tig] = __floats2half2_rn(p10, p11);
        }
        rs0 += __shfl_xor_sync(0xffffffffu, rs0, 1);
        rs0 += __shfl_xor_sync(0xffffffffu, rs0, 2);
        rs1 += __shfl_xor_sync(0xffffffffu, rs1, 1);
        rs1 += __shfl_xor_sync(0xffffffffu, rs1, 2);
        l0 = l0 * c0 + rs0;
        l1 = l1 * c1 + rs1;
#pragma unroll
        for (int nt = 0; nt < 4; nt++) {
            o[nt][0] *= c0; o[nt][1] *= c0;
            o[nt][2] *= c1; o[nt][3] *= c1;
        }
        __syncwarp();

        // O += P V : A = P (pairs along keys), B = V via ldmatrix.trans
#pragma unroll
        for (int ks = 0; ks < 4; ks++) {
            uint32_t a[4];
            a[0] = *(const uint32_t*)&pw[gid * PS_H + ks * 16 + 2 * tig];
            a[1] = *(const uint32_t*)&pw[(gid + 8) * PS_H + ks * 16 + 2 * tig];
            a[2] = *(const uint32_t*)&pw[gid * PS_H + ks * 16 + 8 + 2 * tig];
            a[3] = *(const uint32_t*)&pw[(gid + 8) * PS_H + ks * 16 + 8 + 2 * tig];
#pragma unroll
            for (int nt = 0; nt < 4; nt++) {
                uint32_t b0, b1;
                uint32_t addr = vbase + ((ks * 16 + la) * KS_H + nt * 8) * 2;
                ldsm2t(b0, b1, addr);
                mma_f16(o[nt], a, b0, b1);
            }
        }
        if (nk < 35) CP_WAIT0();
        __syncthreads();
    }

    float i0 = 1.0f / l0, i1 = 1.0f / l1;
    float* AO = g_ao + (size_t)bh * BH_STRIDE;
#pragma unroll
    for (int nt = 0; nt < 4; nt++) {
        float2 lo = make_float2(tf32f(o[nt][0] * i0), tf32f(o[nt][1] * i0));
        float2 hi = make_float2(tf32f(o[nt][2] * i1), tf32f(o[nt][3] * i1));
        *(float2*)&AO[(size_t)qr * 32 + nt * 8 + 2 * tig] = lo;
        *(float2*)&AO[(size_t)(qr + 8) * 32 + nt * 8 + 2 * tig] = hi;
    }
}

// ---------------------------------------------------------------------------
// 7) Output projection via tf32 mma
// ---------------------------------------------------------------------------
__global__ __launch_bounds__(256) void k_proj(const float* __restrict__ bproj,
                                              float* __restrict__ out) {
    __shared__ float wsm[128 * AW_STRIDE];
    __shared__ float bsm2[32 * BX_STRIDE];
    int ntb = blockIdx.x, mt = blockIdx.y, b = blockIdx.z;
    int t = threadIdx.x, warp = t >> 5, lane = t & 31;
    int gid = lane >> 2, tig = lane & 3;
    int n0 = ntb * 64;

    const float* W = g_Wt + 3 * 65536 + mt * 128 * 256;
    const float* AOb = g_ao + (size_t)b * B_STRIDE;

    float s[8][4];
#pragma unroll
    for (int i = 0; i < 8; i++)
#pragma unroll
        for (int j = 0; j < 4; j++) s[i][j] = 0.f;

    for (int kk = 0; kk < 256; kk += 32) {
        if (kk) __syncthreads();
#pragma unroll
        for (int j = 0; j < 4; j++) {
            int idx = t + j * 256;
            int o = idx >> 3, cg = idx & 7;
            *(float4*)&wsm[o * AW_STRIDE + cg * 4] = *(const float4*)&W[o * 256 + kk + cg * 4];
        }
#pragma unroll
        for (int j = 0; j < 8; j++) {
            int idx = t + j * 256;
            int c = idx >> 6, ng = idx & 63;
            int o = kk + c;
            bsm2[c * BX_STRIDE + ng] =
                AOb[((size_t)(o >> 5) * NPIX + n0 + ng) * 32 + (o & 31)];
        }
        __syncthreads();
#pragma unroll
        for (int ks = 0; ks < 4; ks++) {
            uint32_t a[4];
            int ab = (warp * 16 + gid) * AW_STRIDE + ks * 8 + tig;
            a[0] = __float_as_uint(wsm[ab]);
            a[1] = __float_as_uint(wsm[ab + 8 * AW_STRIDE]);
            a[2] = __float_as_uint(wsm[ab + 4]);
            a[3] = __float_as_uint(wsm[ab + 8 * AW_STRIDE + 4]);
#pragma unroll
            for (int nt = 0; nt < 8; nt++) {
                int bbx = (ks * 8 + tig) * BX_STRIDE + nt * 8 + gid;
                mma_tf32(s[nt], a, __float_as_uint(bsm2[bbx]),
                         __float_as_uint(bsm2[bbx + 4 * BX_STRIDE]));
            }
        }
    }
    int o0 = mt * 128 + warp * 16 + gid, o1 = o0 + 8;
    float bp0 = bproj[o0], bp1 = bproj[o1];
#pragma unroll
    for (int nt = 0; nt < 8; nt++) {
        int n = n0 + nt * 8 + 2 * tig;
        *(float2*)&out[((size_t)(b * 256 + o0)) * NPIX + n] =
            make_float2(s[nt][0] + bp0, s[nt][1] + bp0);
        *(float2*)&out[((size_t)(b * 256 + o1)) * NPIX + n] =
            make_float2(s[nt][2] + bp1, s[nt][3] + bp1);
    }
}

// ---------------------------------------------------------------------------
// launch
// ---------------------------------------------------------------------------
extern "C" void kernel_launch(void* const* d_in, const int* in_sizes, int n_in,
                              void* d_out, int out_size) {
    const float* x     = (const float*)d_in[0];
    const float* rgb   = (const float*)d_in[1];
    const float* wq    = (const float*)d_in[2];
    const float* bq    = (const float*)d_in[3];
    const float* wk    = (const float*)d_in[4];
    const float* bk    = (const float*)d_in[5];
    const float* wv    = (const float*)d_in[6];
    const float* bv    = (const float*)d_in[7];
    const float* wproj = (const float*)d_in[8];
    const float* bproj = (const float*)d_in[9];
    const float* c1w   = (const float*)d_in[10];
    const float* c1b   = (const float*)d_in[11];
    const float* c2w   = (const float*)d_in[12];
    const float* c2b   = (const float*)d_in[13];
    const float* alpha = (const float*)d_in[26];

    FilmArgs fa;
    fa.w[0] = (const float*)d_in[14]; fa.b[0] = (const float*)d_in[15];
    fa.w[1] = (const float*)d_in[16]; fa.b[1] = (const float*)d_in[17];
    fa.w[2] = (const float*)d_in[18]; fa.b[2] = (const float*)d_in[19];
    fa.w[3] = (const float*)d_in[20]; fa.b[3] = (const float*)d_in[21];
    fa.w[4] = (const float*)d_in[22]; fa.b[4] = (const float*)d_in[23];
    fa.w[5] = (const float*)d_in[24]; fa.b[5] = (const float*)d_in[25];

    static bool attr_done = false;
    if (!attr_done) {
        cudaFuncSetAttribute(k_attn, cudaFuncAttributeMaxDynamicSharedMemorySize, ATTN_SMEM);
        attr_done = true;
    }

    k_prep<<<256, 256>>>(wq, wk, wv, wproj);
    k_lumabias<<<BSZ, 256>>>(rgb, alpha);
    k_conv1<<<dim3(HID, BSZ), 256>>>(c1w, c1b);
    k_conv2mean<<<dim3(32, BSZ, 6), 96>>>(c2w, c2b);
    k_film<<<dim3(6, BSZ), 256>>>(fa);
    k_qkv<<<dim3(36, 2, 12), 256>>>(x, bq, bk, bv);
    k_attn<<<dim3(18, 32), 256, ATTN_SMEM>>>();
    k_proj<<<dim3(36, 2, 4), 256>>>(bproj, (float*)d_out);
}